// round 12
// baseline (speedup 1.0000x reference)
#include <cuda_runtime.h>
#include <cuda_bf16.h>
#include <cstdint>

#define NN 50000
#define EE 800000
#define HID 128

// Scratch (device globals — no allocation allowed)
__device__ float g_h[(size_t)NN * HID];
__device__ float g_aggr[(size_t)NN * HID];
__device__ float g_P[(size_t)NN * HID];   // h @ W1a (tgt part)
__device__ float g_Q[(size_t)NN * HID];   // h @ W1b (src part)
__device__ float g_rdeg[NN];
__device__ int g_ei_is64;

typedef unsigned long long u64;

#define FMA2(d, a, b) asm("fma.rn.f32x2 %0, %1, %2, %0;" : "+l"(d) : "l"(a), "l"(b))
#define PACK2(d, lo, hi) asm("mov.b64 %0, {%1, %2};" : "=l"(d) : "f"(lo), "f"(hi))
#define UNPACK2(lo, hi, s) asm("mov.b64 {%0, %1}, %2;" : "=f"(lo), "=f"(hi) : "l"(s))

#define RED2(ptr, a, b) \
    asm volatile("red.global.add.v2.f32 [%0], {%1, %2};" \
                 :: "l"(ptr), "f"(a), "f"(b) : "memory")

#define MMA16816(cc, aa, bb) \
    asm volatile("mma.sync.aligned.m16n8k16.row.col.f32.bf16.bf16.f32 " \
                 "{%0,%1,%2,%3}, {%4,%5,%6,%7}, {%8,%9}, {%0,%1,%2,%3};" \
                 : "+f"(cc[0]), "+f"(cc[1]), "+f"(cc[2]), "+f"(cc[3]) \
                 : "r"(aa[0]), "r"(aa[1]), "r"(aa[2]), "r"(aa[3]), \
                   "r"(bb[0]), "r"(bb[1]))

// split float pair into bf16 hi-pack and bf16 residual-pack (x in low bits)
__device__ __forceinline__ void split2(float x, float y, unsigned& hi, unsigned& lo) {
    __nv_bfloat16 xh = __float2bfloat16_rn(x);
    __nv_bfloat16 yh = __float2bfloat16_rn(y);
    __nv_bfloat16 xl = __float2bfloat16_rn(x - __bfloat162float(xh));
    __nv_bfloat16 yl = __float2bfloat16_rn(y - __bfloat162float(yh));
    hi = ((unsigned)__bfloat16_as_ushort(yh) << 16) | __bfloat16_as_ushort(xh);
    lo = ((unsigned)__bfloat16_as_ushort(yl) << 16) | __bfloat16_as_ushort(xl);
}

// perm: k-pair p (0..7) -> u32 slot so that (tig, tig+4) are adjacent
__device__ __forceinline__ int permp(int p) { return 2 * (p & 3) + (p >> 2); }

__device__ __forceinline__ int load_ei(const void* ei, size_t idx, int is64) {
    int v = is64 ? (int)((const long long*)ei)[idx] : ((const int*)ei)[idx];
    return min(max(v, 0), NN - 1);
}

// ---------------------------------------------------------------------------
// init_aggr: zero g_aggr AND probe edge_index dtype (block 0, thread 0)
// ---------------------------------------------------------------------------
__global__ void init_aggr_kernel(const unsigned* __restrict__ raw) {
    size_t i = (size_t)blockIdx.x * blockDim.x + threadIdx.x;
    if (i < (size_t)NN * HID) g_aggr[i] = 0.f;
    if (blockIdx.x == 0 && threadIdx.x == 0) {
        int is64 = 1;
        for (int k = 0; k < 64; k++)
            if (raw[2 * k + 1] != 0u) { is64 = 0; break; }
        g_ei_is64 = is64;
    }
}

// ---------------------------------------------------------------------------
// Encoder
// ---------------------------------------------------------------------------
__global__ void enc_kernel(const float* __restrict__ x, const float* __restrict__ W,
                           const float* __restrict__ b, const float* __restrict__ g,
                           const float* __restrict__ beta) {
    int node = blockIdx.x;
    int t = threadIdx.x;
    __shared__ float sx[32];
    __shared__ float red[8];
    if (t < 32) sx[t] = x[node * 32 + t];
    __syncthreads();
    float acc = b[t];
#pragma unroll
    for (int k = 0; k < 32; k++) acc = fmaf(sx[k], W[k * HID + t], acc);
    acc = fmaxf(acc, 0.f);
    float s = acc, sq = acc * acc;
#pragma unroll
    for (int o = 16; o; o >>= 1) {
        s += __shfl_xor_sync(0xffffffffu, s, o);
        sq += __shfl_xor_sync(0xffffffffu, sq, o);
    }
    int w = t >> 5;
    if ((t & 31) == 0) { red[w] = s; red[4 + w] = sq; }
    __syncthreads();
    s = red[0] + red[1] + red[2] + red[3];
    sq = red[4] + red[5] + red[6] + red[7];
    float mu = s * (1.f / HID);
    float var = sq * (1.f / HID) - mu * mu;
    g_h[(size_t)node * HID + t] = (acc - mu) * rsqrtf(var + 1e-5f) * g[t] + beta[t];
}

// ---------------------------------------------------------------------------
// Degree helpers
// ---------------------------------------------------------------------------
__global__ void zero_deg_kernel() {
    int i = blockIdx.x * blockDim.x + threadIdx.x;
    if (i < NN) g_rdeg[i] = 0.f;
}
__global__ void deg_kernel(const void* __restrict__ ei) {
    int e = blockIdx.x * blockDim.x + threadIdx.x;
    int is64 = g_ei_is64;
    if (e < EE) atomicAdd(&g_rdeg[load_ei(ei, (size_t)EE + e, is64)], 1.f);
}
__global__ void rdeg_kernel() {
    int i = blockIdx.x * blockDim.x + threadIdx.x;
    if (i < NN) g_rdeg[i] = 1.f / fmaxf(g_rdeg[i], 1.f);
}

// ---------------------------------------------------------------------------
// Node GEMM (merged P/Q): blockIdx.y selects W half and output buffer
//   y=0: P = g_h @ W1[0:128]     y=1: Q = g_h @ W1[128:256]
// ---------------------------------------------------------------------------
__global__ void __launch_bounds__(256)
nodemm2_kernel(const float* __restrict__ W1, float* __restrict__ P, float* __restrict__ Q) {
    __shared__ __align__(16) float Ast[16 * 65];
    __shared__ __align__(16) float Bs[16 * 128];

    const float* W = W1 + (size_t)blockIdx.y * 128 * HID;
    float* out = blockIdx.y ? Q : P;

    int tid = threadIdx.x;
    int tx = tid & 15, ty = tid >> 4;
    const int col0 = tx * 8, row0 = ty * 4;
    int n0 = blockIdx.x * 64;
    int le = tid >> 2;
    int kb = (tid & 3) * 4;
    int lnode = min(n0 + le, NN - 1);

    u64 acc[4][4];
#pragma unroll
    for (int i = 0; i < 4; i++)
#pragma unroll
        for (int j = 0; j < 4; j++) acc[i][j] = 0ull;

    for (int c = 0; c < 8; c++) {
        const float* ap = g_h + (size_t)lnode * HID + c * 16 + kb;
        float4 v = *(const float4*)ap;
        const float* wp = W + c * 16 * 128;
        float4 w0 = *(const float4*)(wp + tid * 8);
        float4 w1 = *(const float4*)(wp + tid * 8 + 4);
        __syncthreads();
        Ast[(kb + 0) * 65 + le] = v.x;
        Ast[(kb + 1) * 65 + le] = v.y;
        Ast[(kb + 2) * 65 + le] = v.z;
        Ast[(kb + 3) * 65 + le] = v.w;
        *(float4*)(Bs + tid * 8) = w0;
        *(float4*)(Bs + tid * 8 + 4) = w1;
        __syncthreads();
#pragma unroll
        for (int kk = 0; kk < 16; kk++) {
            u64 a2[4];
#pragma unroll
            for (int i = 0; i < 4; i++) {
                float a = Ast[kk * 65 + row0 + i];
                PACK2(a2[i], a, a);
            }
            ulonglong2 qq0 = *(const ulonglong2*)(Bs + kk * 128 + col0);
            ulonglong2 qq1 = *(const ulonglong2*)(Bs + kk * 128 + col0 + 4);
            u64 bp[4] = {qq0.x, qq0.y, qq1.x, qq1.y};
#pragma unroll
            for (int i = 0; i < 4; i++)
#pragma unroll
                for (int j = 0; j < 4; j++) FMA2(acc[i][j], a2[i], bp[j]);
        }
    }

#pragma unroll
    for (int i = 0; i < 4; i++) {
        int node = n0 + row0 + i;
        if (node < NN) {
            float f[8];
#pragma unroll
            for (int j = 0; j < 4; j++) UNPACK2(f[2 * j], f[2 * j + 1], acc[i][j]);
            float4 o0 = {f[0], f[1], f[2], f[3]};
            float4 o1 = {f[4], f[5], f[6], f[7]};
            *(float4*)(out + (size_t)node * HID + col0) = o0;
            *(float4*)(out + (size_t)node * HID + col0 + 4) = o1;
        }
    }
}

// ---------------------------------------------------------------------------
// Message kernel (R9-identical, validated 1994us):
//   pre = P[tgt] + Q[src] + ea @ W1c + b1     (GEMM1 K=16)
//   hidden = ReLU(pre)
//   m = hidden @ W2 + b2                      (K=128)
//   red.v2(g_aggr[tgt], m)
// ---------------------------------------------------------------------------
__global__ void __launch_bounds__(256)
msg_kernel(const void* __restrict__ ei, const float* __restrict__ ea,
           const float* __restrict__ W1c, const float* __restrict__ b1,
           const float* __restrict__ W2, const float* __restrict__ b2) {
    __shared__ __align__(16) unsigned sB_hi[128 * 10];
    __shared__ __align__(16) unsigned sB_lo[128 * 10];
    __shared__ __align__(16) unsigned sH_hi[64 * 70];
    __shared__ __align__(16) unsigned sH_lo[64 * 70];
    __shared__ int s_src[64];
    __shared__ int s_tgt[64];

    int tid = threadIdx.x;
    int lane = tid & 31, wid = tid >> 5;
    int gid = lane >> 2, tig = lane & 3;
    int wm = wid & 3, wn = wid >> 2;
    int e0 = blockIdx.x * 64;

    int le = tid >> 2;       // edge row 0..63
    int kq = tid & 3;        // float-quad within 16-k panel
    int bn = tid & 127;      // output column
    int bkh = tid >> 7;      // k-half (0/1)

    int is64 = g_ei_is64;
    if (tid < 64) s_src[tid] = load_ei(ei, (size_t)e0 + tid, is64);
    else if (tid < 128) s_tgt[tid - 64] = load_ei(ei, (size_t)EE + e0 + (tid - 64), is64);

    float acc[8][4];
#pragma unroll
    for (int t = 0; t < 8; t++)
#pragma unroll
        for (int j = 0; j < 4; j++) acc[t][j] = 0.f;

    unsigned* sA_hi = sH_hi;  // alias: [64][10]
    unsigned* sA_lo = sH_lo;

    const int q0 = permp(2 * kq), q1 = permp(2 * kq + 1);
    const int arow0 = (wm * 16 + gid) * 10 + 2 * tig;

    __syncthreads();

    // ================= GEMM1: single K=16 panel (ea @ W1c) =================
    {
        const float* ap = ea + (size_t)(e0 + le) * 16 + kq * 4;
        float4 v = *(const float4*)ap;
        float w[8];
        const float* wp = W1c + (size_t)(bkh * 8) * HID + bn;
#pragma unroll
        for (int kk = 0; kk < 8; kk++) w[kk] = wp[(size_t)kk * HID];

        unsigned h0, l0, h1, l1;
        split2(v.x, v.y, h0, l0);
        split2(v.z, v.w, h1, l1);
        sA_hi[le * 10 + q0] = h0; sA_lo[le * 10 + q0] = l0;
        sA_hi[le * 10 + q1] = h1; sA_lo[le * 10 + q1] = l1;
#pragma unroll
        for (int j = 0; j < 4; j++) {
            unsigned hi, lo;
            split2(w[2 * j], w[2 * j + 1], hi, lo);
            int q = permp(bkh * 4 + j);
            sB_hi[bn * 10 + q] = hi;
            sB_lo[bn * 10 + q] = lo;
        }
        __syncthreads();

        uint2 AH0 = *(uint2*)&sA_hi[arow0];
        uint2 AH1 = *(uint2*)&sA_hi[arow0 + 80];
        uint2 AL0 = *(uint2*)&sA_lo[arow0];
        uint2 AL1 = *(uint2*)&sA_lo[arow0 + 80];
        unsigned ah[4] = {AH0.x, AH1.x, AH0.y, AH1.y};
        unsigned al[4] = {AL0.x, AL1.x, AL0.y, AL1.y};
#pragma unroll
        for (int t = 0; t < 8; t++) {
            int br = (wn * 64 + t * 8 + gid) * 10 + 2 * tig;
            uint2 BH = *(uint2*)&sB_hi[br];
            uint2 BL = *(uint2*)&sB_lo[br];
            unsigned bh[2] = {BH.x, BH.y};
            unsigned bl[2] = {BL.x, BL.y};
            MMA16816(acc[t], ah, bh);
            MMA16816(acc[t], ah, bl);
            MMA16816(acc[t], al, bh);
        }
    }

    __syncthreads();  // GEMM1 mma reads done before sH overwrite

    // ---- += P[tgt] + Q[src] + b1, ReLU -> sH (packed for GEMM2 A-frags) ----
    {
        int r0 = wm * 16 + gid;
        int n0t = s_tgt[r0], n0s = s_src[r0];
        int n1t = s_tgt[r0 + 8], n1s = s_src[r0 + 8];
        const float* P0 = g_P + (size_t)n0t * HID;
        const float* Q0 = g_Q + (size_t)n0s * HID;
        const float* P1 = g_P + (size_t)n1t * HID;
        const float* Q1 = g_Q + (size_t)n1s * HID;
#pragma unroll
        for (int t = 0; t < 8; t++) {
            int col = wn * 64 + t * 8 + tig * 2;
            float bb0 = b1[col], bb1 = b1[col + 1];
            float2 p0 = *(const float2*)(P0 + col);
            float2 qq0 = *(const float2*)(Q0 + col);
            float2 p1 = *(const float2*)(P1 + col);
            float2 qq1 = *(const float2*)(Q1 + col);
            float x0 = fmaxf(acc[t][0] + bb0 + p0.x + qq0.x, 0.f);
            float x1 = fmaxf(acc[t][1] + bb1 + p0.y + qq0.y, 0.f);
            float x2 = fmaxf(acc[t][2] + bb0 + p1.x + qq1.x, 0.f);
            float x3 = fmaxf(acc[t][3] + bb1 + p1.y + qq1.y, 0.f);
            int c2 = col >> 4;
            int q = permp((t & 1) * 4 + tig);
            unsigned hi0, lo0, hi1, lo1;
            split2(x0, x1, hi0, lo0);
            split2(x2, x3, hi1, lo1);
            sH_hi[r0 * 70 + c2 * 8 + q] = hi0;
            sH_lo[r0 * 70 + c2 * 8 + q] = lo0;
            sH_hi[(r0 + 8) * 70 + c2 * 8 + q] = hi1;
            sH_lo[(r0 + 8) * 70 + c2 * 8 + q] = lo1;
#pragma unroll
            for (int j = 0; j < 4; j++) acc[t][j] = 0.f;
        }
    }
    __syncthreads();

    // ================= GEMM2: K=128, 8 panels =================
    for (int c = 0; c < 8; c++) {
        float w[8];
        const float* wp = W2 + (size_t)(c * 16 + bkh * 8) * HID + bn;
#pragma unroll
        for (int kk = 0; kk < 8; kk++) w[kk] = wp[(size_t)kk * HID];
        __syncthreads();
#pragma unroll
        for (int j = 0; j < 4; j++) {
            unsigned hi, lo;
            split2(w[2 * j], w[2 * j + 1], hi, lo);
            int q = permp(bkh * 4 + j);
            sB_hi[bn * 10 + q] = hi;
            sB_lo[bn * 10 + q] = lo;
        }
        __syncthreads();

        int ar = (wm * 16 + gid) * 70 + c * 8 + 2 * tig;
        uint2 AH0 = *(uint2*)&sH_hi[ar];
        uint2 AH1 = *(uint2*)&sH_hi[ar + 560];
        uint2 AL0 = *(uint2*)&sH_lo[ar];
        uint2 AL1 = *(uint2*)&sH_lo[ar + 560];
        unsigned ah[4] = {AH0.x, AH1.x, AH0.y, AH1.y};
        unsigned al[4] = {AL0.x, AL1.x, AL0.y, AL1.y};
#pragma unroll
        for (int t = 0; t < 8; t++) {
            int br = (wn * 64 + t * 8 + gid) * 10 + 2 * tig;
            uint2 BH = *(uint2*)&sB_hi[br];
            uint2 BL = *(uint2*)&sB_lo[br];
            unsigned bh[2] = {BH.x, BH.y};
            unsigned bl[2] = {BL.x, BL.y};
            MMA16816(acc[t], ah, bh);
            MMA16816(acc[t], ah, bl);
            MMA16816(acc[t], al, bh);
        }
    }

    // ---- scatter: m + b2 -> g_aggr[tgt] ----
    {
        int r0 = wm * 16 + gid;
        int n0 = s_tgt[r0], n1 = s_tgt[r0 + 8];
#pragma unroll
        for (int t = 0; t < 8; t++) {
            int col = wn * 64 + t * 8 + tig * 2;
            float bb0 = b2[col], bb1 = b2[col + 1];
            RED2(g_aggr + (size_t)n0 * HID + col, acc[t][0] + bb0, acc[t][1] + bb1);
            RED2(g_aggr + (size_t)n1 * HID + col, acc[t][2] + bb0, acc[t][3] + bb1);
        }
    }
}

// ---------------------------------------------------------------------------
// Update kernel (unchanged, known-good)
// ---------------------------------------------------------------------------
__global__ void __launch_bounds__(256)
upd_kernel(const float* __restrict__ W1, const float* __restrict__ b1,
           const float* __restrict__ W2, const float* __restrict__ b2,
           const float* __restrict__ lng, const float* __restrict__ lnb) {
    __shared__ __align__(16) float Ast[16 * 65];
    __shared__ __align__(16) float Bs[16 * 128];
    __shared__ __align__(16) float Hs[64 * 132];

    int tid = threadIdx.x;
    int tx = tid & 15, ty = tid >> 4;
    const int col0 = tx * 8, row0 = ty * 4;
    int n0 = blockIdx.x * 64;
    int le = tid >> 2;
    int kb = (tid & 3) * 4;
    int lnode = min(n0 + le, NN - 1);
    float rd = g_rdeg[lnode];

    u64 acc[4][4];
#pragma unroll
    for (int i = 0; i < 4; i++)
#pragma unroll
        for (int j = 0; j < 4; j++) acc[i][j] = 0ull;

    float b1v[8], b2v[8];
#pragma unroll
    for (int j = 0; j < 8; j++) { b1v[j] = b1[col0 + j]; b2v[j] = b2[col0 + j]; }

    for (int c = 0; c < 16; c++) {
        const float* ap = (c < 8) ? g_h + (size_t)lnode * HID + c * 16 + kb
                                  : g_aggr + (size_t)lnode * HID + (c - 8) * 16 + kb;
        float4 v = *(const float4*)ap;
        if (c >= 8) { v.x *= rd; v.y *= rd; v.z *= rd; v.w *= rd; }
        const float* wp = W1 + c * 16 * 128;
        float4 w0 = *(const float4*)(wp + tid * 8);
        float4 w1 = *(const float4*)(wp + tid * 8 + 4);
        __syncthreads();
        Ast[(kb + 0) * 65 + le] = v.x;
        Ast[(kb + 1) * 65 + le] = v.y;
        Ast[(kb + 2) * 65 + le] = v.z;
        Ast[(kb + 3) * 65 + le] = v.w;
        *(float4*)(Bs + tid * 8) = w0;
        *(float4*)(Bs + tid * 8 + 4) = w1;
        __syncthreads();
#pragma unroll
        for (int kk = 0; kk < 16; kk++) {
            u64 a2[4];
#pragma unroll
            for (int i = 0; i < 4; i++) {
                float a = Ast[kk * 65 + row0 + i];
                PACK2(a2[i], a, a);
            }
            ulonglong2 qq0 = *(const ulonglong2*)(Bs + kk * 128 + col0);
            ulonglong2 qq1 = *(const ulonglong2*)(Bs + kk * 128 + col0 + 4);
            u64 bp[4] = {qq0.x, qq0.y, qq1.x, qq1.y};
#pragma unroll
            for (int i = 0; i < 4; i++)
#pragma unroll
                for (int j = 0; j < 4; j++) FMA2(acc[i][j], a2[i], bp[j]);
        }
    }

#pragma unroll
    for (int i = 0; i < 4; i++) {
        float* hrow = Hs + (row0 + i) * 132;
#pragma unroll
        for (int j = 0; j < 4; j++) {
            float lo, hi;
            UNPACK2(lo, hi, acc[i][j]);
            hrow[col0 + 2 * j]     = fmaxf(lo + b1v[2 * j], 0.f);
            hrow[col0 + 2 * j + 1] = fmaxf(hi + b1v[2 * j + 1], 0.f);
            acc[i][j] = 0ull;
        }
    }
    __syncthreads();

    for (int c = 0; c < 8; c++) {
        const float* wp = W2 + c * 16 * 128;
        float4 w0 = *(const float4*)(wp + tid * 8);
        float4 w1 = *(const float4*)(wp + tid * 8 + 4);
        __syncthreads();
        *(float4*)(Bs + tid * 8) = w0;
        *(float4*)(Bs + tid * 8 + 4) = w1;
        __syncthreads();
#pragma unroll
        for (int kk = 0; kk < 16; kk++) {
            int k = c * 16 + kk;
            u64 a2[4];
#pragma unroll
            for (int i = 0; i < 4; i++) {
                float a = Hs[(row0 + i) * 132 + k];
                PACK2(a2[i], a, a);
            }
            ulonglong2 qq0 = *(const ulonglong2*)(Bs + kk * 128 + col0);
            ulonglong2 qq1 = *(const ulonglong2*)(Bs + kk * 128 + col0 + 4);
            u64 bp[4] = {qq0.x, qq0.y, qq1.x, qq1.y};
#pragma unroll
            for (int i = 0; i < 4; i++)
#pragma unroll
                for (int j = 0; j < 4; j++) FMA2(acc[i][j], a2[i], bp[j]);
        }
    }
    __syncthreads();

#pragma unroll
    for (int i = 0; i < 4; i++) {
        int node = min(n0 + row0 + i, NN - 1);
        const float* hold = g_h + (size_t)node * HID + col0;
        float* vrow = Hs + (row0 + i) * 132;
#pragma unroll
        for (int j = 0; j < 4; j++) {
            float lo, hi;
            UNPACK2(lo, hi, acc[i][j]);
            vrow[col0 + 2 * j]     = lo + b2v[2 * j]     + hold[2 * j];
            vrow[col0 + 2 * j + 1] = hi + b2v[2 * j + 1] + hold[2 * j + 1];
        }
    }
    __syncthreads();

    int lane = tid & 31, w = tid >> 5;
    for (int r = w; r < 64; r += 8) {
        int node = n0 + r;
        float4 v = *(float4*)(Hs + r * 132 + lane * 4);
        float s = v.x + v.y + v.z + v.w;
        float sq = fmaf(v.x, v.x, fmaf(v.y, v.y, fmaf(v.z, v.z, v.w * v.w)));
#pragma unroll
        for (int o = 16; o; o >>= 1) {
            s += __shfl_xor_sync(0xffffffffu, s, o);
            sq += __shfl_xor_sync(0xffffffffu, sq, o);
        }
        float mu = s * (1.f / HID);
        float var = sq * (1.f / HID) - mu * mu;
        float rstd = rsqrtf(var + 1e-5f);
        if (node < NN) {
            int cc = lane * 4;
            float4 o;
            o.x = (v.x - mu) * rstd * lng[cc + 0] + lnb[cc + 0];
            o.y = (v.y - mu) * rstd * lng[cc + 1] + lnb[cc + 1];
            o.z = (v.z - mu) * rstd * lng[cc + 2] + lnb[cc + 2];
            o.w = (v.w - mu) * rstd * lng[cc + 3] + lnb[cc + 3];
            *(float4*)(g_h + (size_t)node * HID + cc) = o;
        }
    }
}

// ---------------------------------------------------------------------------
// Head kernel (unchanged, known-good)
// ---------------------------------------------------------------------------
__global__ void __launch_bounds__(256)
head_kernel(const float* __restrict__ W, const float* __restrict__ b,
            float* __restrict__ out) {
    __shared__ __align__(16) float Ast[16 * 65];
    __shared__ __align__(16) float Bs[16 * 128];

    int tid = threadIdx.x;
    int tx = tid & 15, ty = tid >> 4;
    const int col0 = tx * 8, row0 = ty * 4;
    int n0 = blockIdx.x * 64;
    int le = tid >> 2;
    int kb = (tid & 3) * 4;
    int lnode = min(n0 + le, NN - 1);

    u64 acc[4][4];
#pragma unroll
    for (int i = 0; i < 4; i++)
#pragma unroll
        for (int j = 0; j < 4; j++) acc[i][j] = 0ull;

    float bv[8];
#pragma unroll
    for (int j = 0; j < 8; j++) bv[j] = b[col0 + j];

    for (int c = 0; c < 8; c++) {
        const float* ap = g_h + (size_t)lnode * HID + c * 16 + kb;
        float4 v = *(const float4*)ap;
        const float* wp = W + c * 16 * 128;
        float4 w0 = *(const float4*)(wp + tid * 8);
        float4 w1 = *(const float4*)(wp + tid * 8 + 4);
        __syncthreads();
        Ast[(kb + 0) * 65 + le] = v.x;
        Ast[(kb + 1) * 65 + le] = v.y;
        Ast[(kb + 2) * 65 + le] = v.z;
        Ast[(kb + 3) * 65 + le] = v.w;
        *(float4*)(Bs + tid * 8) = w0;
        *(float4*)(Bs + tid * 8 + 4) = w1;
        __syncthreads();
#pragma unroll
        for (int kk = 0; kk < 16; kk++) {
            u64 a2[4];
#pragma unroll
            for (int i = 0; i < 4; i++) {
                float a = Ast[kk * 65 + row0 + i];
                PACK2(a2[i], a, a);
            }
            ulonglong2 qq0 = *(const ulonglong2*)(Bs + kk * 128 + col0);
            ulonglong2 qq1 = *(const ulonglong2*)(Bs + kk * 128 + col0 + 4);
            u64 bp[4] = {qq0.x, qq0.y, qq1.x, qq1.y};
#pragma unroll
            for (int i = 0; i < 4; i++)
#pragma unroll
                for (int j = 0; j < 4; j++) FMA2(acc[i][j], a2[i], bp[j]);
        }
    }

#pragma unroll
    for (int i = 0; i < 4; i++) {
        int node = n0 + row0 + i;
        if (node < NN) {
            float f[8];
#pragma unroll
            for (int j = 0; j < 4; j++) UNPACK2(f[2 * j], f[2 * j + 1], acc[i][j]);
            float4 o0 = {f[0] + bv[0], f[1] + bv[1], f[2] + bv[2], f[3] + bv[3]};
            float4 o1 = {f[4] + bv[4], f[5] + bv[5], f[6] + bv[6], f[7] + bv[7]};
            *(float4*)(out + (size_t)node * HID + col0) = o0;
            *(float4*)(out + (size_t)node * HID + col0 + 4) = o1;
        }
    }
}

// ---------------------------------------------------------------------------
extern "C" void kernel_launch(void* const* d_in, const int* in_sizes, int n_in,
                              void* d_out, int out_size) {
    const float* x = (const float*)d_in[0];
    const void* ei = d_in[1];
    const float* ea = (const float*)d_in[2];
    const float* enc_W = (const float*)d_in[3];
    const float* enc_b = (const float*)d_in[4];
    const float* enc_g = (const float*)d_in[5];
    const float* enc_beta = (const float*)d_in[6];
    const float* msg_W1 = (const float*)d_in[7];
    const float* msg_b1 = (const float*)d_in[8];
    const float* msg_W2 = (const float*)d_in[9];
    const float* msg_b2 = (const float*)d_in[10];
    const float* upd_W1 = (const float*)d_in[11];
    const float* upd_b1 = (const float*)d_in[12];
    const float* upd_W2 = (const float*)d_in[13];
    const float* upd_b2 = (const float*)d_in[14];
    const float* ln_g = (const float*)d_in[15];
    const float* ln_beta = (const float*)d_in[16];
    const float* head_W = (const float*)d_in[17];
    const float* head_b = (const float*)d_in[18];
    float* out = (float*)d_out;

    static float* dP = nullptr;
    static float* dQ = nullptr;
    if (!dP) {
        cudaGetSymbolAddress((void**)&dP, g_P);
        cudaGetSymbolAddress((void**)&dQ, g_Q);
    }

    const int NB = (NN + 63) / 64;
    const int ZB = ((size_t)NN * HID + 255) / 256;

    // ---- layer 0; msg at launch index 3 so ncu profiles it ----
    init_aggr_kernel<<<ZB, 256>>>((const unsigned*)ei);             // 0: zero aggr + dtype probe
    enc_kernel<<<NN, 128>>>(x, enc_W, enc_b, enc_g, enc_beta);      // 1
    nodemm2_kernel<<<dim3(NB, 2), 256>>>(msg_W1, dP, dQ);           // 2: P and Q
    msg_kernel<<<EE / 64, 256>>>(                                   // 3 <- profiled
        ei, ea,
        msg_W1 + (size_t)256 * HID, msg_b1,
        msg_W2, msg_b2);
    zero_deg_kernel<<<(NN + 255) / 256, 256>>>();                   // 4
    deg_kernel<<<(EE + 255) / 256, 256>>>(ei);                      // 5
    rdeg_kernel<<<(NN + 255) / 256, 256>>>();                       // 6
    upd_kernel<<<NB, 256>>>(                                        // 7
        upd_W1, upd_b1, upd_W2, upd_b2, ln_g, ln_beta);

    // ---- layer 1 ----
    const float* W1_1 = msg_W1 + (size_t)272 * HID;
    nodemm2_kernel<<<dim3(NB, 2), 256>>>(W1_1, dP, dQ);             // 8
    init_aggr_kernel<<<ZB, 256>>>((const unsigned*)ei);             // 9
    msg_kernel<<<EE / 64, 256>>>(                                   // 10
        ei, ea,
        W1_1 + (size_t)256 * HID, msg_b1 + HID,
        msg_W2 + (size_t)HID * HID, msg_b2 + HID);
    upd_kernel<<<NB, 256>>>(                                        // 11
        upd_W1 + (size_t)256 * HID, upd_b1 + HID,
        upd_W2 + (size_t)HID * HID, upd_b2 + HID,
        ln_g + HID, ln_beta + HID);

    head_kernel<<<NB, 256>>>(head_W, head_b, out);                  // 12
}

// round 13
// speedup vs baseline: 1.2782x; 1.2782x over previous
#include <cuda_runtime.h>
#include <cuda_bf16.h>
#include <cstdint>

#define NN 50000
#define EE 800000
#define HID 128

// Scratch (device globals — no allocation allowed)
__device__ float g_h[(size_t)NN * HID];
__device__ float g_aggr[(size_t)NN * HID];
__device__ float g_P[(size_t)NN * HID];
__device__ float g_Q[(size_t)NN * HID];
__device__ float g_rdeg[NN];
__device__ int g_ei_is64;

typedef unsigned long long u64;

#define RED2(ptr, a, b) \
    asm volatile("red.global.add.v2.f32 [%0], {%1, %2};" \
                 :: "l"(ptr), "f"(a), "f"(b) : "memory")

#define MMA16816(cc, aa, bb) \
    asm volatile("mma.sync.aligned.m16n8k16.row.col.f32.bf16.bf16.f32 " \
                 "{%0,%1,%2,%3}, {%4,%5,%6,%7}, {%8,%9}, {%0,%1,%2,%3};" \
                 : "+f"(cc[0]), "+f"(cc[1]), "+f"(cc[2]), "+f"(cc[3]) \
                 : "r"(aa[0]), "r"(aa[1]), "r"(aa[2]), "r"(aa[3]), \
                   "r"(bb[0]), "r"(bb[1]))

// split float pair into bf16 hi-pack and bf16 residual-pack (x in low bits)
__device__ __forceinline__ void split2(float x, float y, unsigned& hi, unsigned& lo) {
    __nv_bfloat16 xh = __float2bfloat16_rn(x);
    __nv_bfloat16 yh = __float2bfloat16_rn(y);
    __nv_bfloat16 xl = __float2bfloat16_rn(x - __bfloat162float(xh));
    __nv_bfloat16 yl = __float2bfloat16_rn(y - __bfloat162float(yh));
    hi = ((unsigned)__bfloat16_as_ushort(yh) << 16) | __bfloat16_as_ushort(xh);
    lo = ((unsigned)__bfloat16_as_ushort(yl) << 16) | __bfloat16_as_ushort(xl);
}

// perm: k-pair p (0..7) -> u32 slot so that (tig, tig+4) are adjacent
__device__ __forceinline__ int permp(int p) { return 2 * (p & 3) + (p >> 2); }

__device__ __forceinline__ int load_ei(const void* ei, size_t idx, int is64) {
    int v = is64 ? (int)((const long long*)ei)[idx] : ((const int*)ei)[idx];
    return min(max(v, 0), NN - 1);
}

// ---------------------------------------------------------------------------
__global__ void init_aggr_kernel(const unsigned* __restrict__ raw) {
    size_t i = (size_t)blockIdx.x * blockDim.x + threadIdx.x;
    if (i < (size_t)NN * HID) g_aggr[i] = 0.f;
    if (blockIdx.x == 0 && threadIdx.x == 0) {
        int is64 = 1;
        for (int k = 0; k < 64; k++)
            if (raw[2 * k + 1] != 0u) { is64 = 0; break; }
        g_ei_is64 = is64;
    }
}

// ---------------------------------------------------------------------------
__global__ void enc_kernel(const float* __restrict__ x, const float* __restrict__ W,
                           const float* __restrict__ b, const float* __restrict__ g,
                           const float* __restrict__ beta) {
    int node = blockIdx.x;
    int t = threadIdx.x;
    __shared__ float sx[32];
    __shared__ float red[8];
    if (t < 32) sx[t] = x[node * 32 + t];
    __syncthreads();
    float acc = b[t];
#pragma unroll
    for (int k = 0; k < 32; k++) acc = fmaf(sx[k], W[k * HID + t], acc);
    acc = fmaxf(acc, 0.f);
    float s = acc, sq = acc * acc;
#pragma unroll
    for (int o = 16; o; o >>= 1) {
        s += __shfl_xor_sync(0xffffffffu, s, o);
        sq += __shfl_xor_sync(0xffffffffu, sq, o);
    }
    int w = t >> 5;
    if ((t & 31) == 0) { red[w] = s; red[4 + w] = sq; }
    __syncthreads();
    s = red[0] + red[1] + red[2] + red[3];
    sq = red[4] + red[5] + red[6] + red[7];
    float mu = s * (1.f / HID);
    float var = sq * (1.f / HID) - mu * mu;
    g_h[(size_t)node * HID + t] = (acc - mu) * rsqrtf(var + 1e-5f) * g[t] + beta[t];
}

__global__ void zero_deg_kernel() {
    int i = blockIdx.x * blockDim.x + threadIdx.x;
    if (i < NN) g_rdeg[i] = 0.f;
}
__global__ void deg_kernel(const void* __restrict__ ei) {
    int e = blockIdx.x * blockDim.x + threadIdx.x;
    int is64 = g_ei_is64;
    if (e < EE) atomicAdd(&g_rdeg[load_ei(ei, (size_t)EE + e, is64)], 1.f);
}
__global__ void rdeg_kernel() {
    int i = blockIdx.x * blockDim.x + threadIdx.x;
    if (i < NN) g_rdeg[i] = 1.f / fmaxf(g_rdeg[i], 1.f);
}

// ---------------------------------------------------------------------------
// Node GEMM (mma): blockIdx.y: 0 -> P = h@W1[0:128], 1 -> Q = h@W1[128:256]
// 64 rows x 128 cols per block; same fragment scheme as msg (validated).
// ---------------------------------------------------------------------------
__global__ void __launch_bounds__(256)
nodemm2_kernel(const float* __restrict__ W1, float* __restrict__ P, float* __restrict__ Q) {
    __shared__ __align__(16) unsigned sB_hi[128 * 10];
    __shared__ __align__(16) unsigned sB_lo[128 * 10];
    __shared__ __align__(16) unsigned sA_hi[64 * 10];
    __shared__ __align__(16) unsigned sA_lo[64 * 10];

    const float* W = W1 + (size_t)blockIdx.y * 128 * HID;
    float* out = blockIdx.y ? Q : P;

    int tid = threadIdx.x;
    int lane = tid & 31, wid = tid >> 5;
    int gid = lane >> 2, tig = lane & 3;
    int wm = wid & 3, wn = wid >> 2;
    int n0 = blockIdx.x * 64;

    int le = tid >> 2, kq = tid & 3;
    int bn = tid & 127, bkh = tid >> 7;
    int lnode = min(n0 + le, NN - 1);

    const int q0 = permp(2 * kq), q1 = permp(2 * kq + 1);
    const int arow0 = (wm * 16 + gid) * 10 + 2 * tig;

    float acc[8][4];
#pragma unroll
    for (int t = 0; t < 8; t++)
#pragma unroll
        for (int j = 0; j < 4; j++) acc[t][j] = 0.f;

    for (int c = 0; c < 8; c++) {
        float4 v = *(const float4*)(g_h + (size_t)lnode * HID + c * 16 + kq * 4);
        float w[8];
        const float* wp = W + (size_t)(c * 16 + bkh * 8) * HID + bn;
#pragma unroll
        for (int kk = 0; kk < 8; kk++) w[kk] = wp[(size_t)kk * HID];
        __syncthreads();
        unsigned h0, l0, h1, l1;
        split2(v.x, v.y, h0, l0);
        split2(v.z, v.w, h1, l1);
        sA_hi[le * 10 + q0] = h0; sA_lo[le * 10 + q0] = l0;
        sA_hi[le * 10 + q1] = h1; sA_lo[le * 10 + q1] = l1;
#pragma unroll
        for (int j = 0; j < 4; j++) {
            unsigned hi, lo;
            split2(w[2 * j], w[2 * j + 1], hi, lo);
            int q = permp(bkh * 4 + j);
            sB_hi[bn * 10 + q] = hi;
            sB_lo[bn * 10 + q] = lo;
        }
        __syncthreads();
        uint2 AH0 = *(uint2*)&sA_hi[arow0];
        uint2 AH1 = *(uint2*)&sA_hi[arow0 + 80];
        uint2 AL0 = *(uint2*)&sA_lo[arow0];
        uint2 AL1 = *(uint2*)&sA_lo[arow0 + 80];
        unsigned ah[4] = {AH0.x, AH1.x, AH0.y, AH1.y};
        unsigned al[4] = {AL0.x, AL1.x, AL0.y, AL1.y};
#pragma unroll
        for (int t = 0; t < 8; t++) {
            int br = (wn * 64 + t * 8 + gid) * 10 + 2 * tig;
            uint2 BH = *(uint2*)&sB_hi[br];
            uint2 BL = *(uint2*)&sB_lo[br];
            unsigned bh[2] = {BH.x, BH.y};
            unsigned bl[2] = {BL.x, BL.y};
            MMA16816(acc[t], ah, bh);
            MMA16816(acc[t], ah, bl);
            MMA16816(acc[t], al, bh);
        }
    }

    int r0 = wm * 16 + gid;
    int node0 = n0 + r0, node1 = n0 + r0 + 8;
#pragma unroll
    for (int t = 0; t < 8; t++) {
        int col = wn * 64 + t * 8 + tig * 2;
        if (node0 < NN) *(float2*)(out + (size_t)node0 * HID + col) = make_float2(acc[t][0], acc[t][1]);
        if (node1 < NN) *(float2*)(out + (size_t)node1 * HID + col) = make_float2(acc[t][2], acc[t][3]);
    }
}

// ---------------------------------------------------------------------------
// Message kernel (R9/R12-identical, validated)
// ---------------------------------------------------------------------------
__global__ void __launch_bounds__(256)
msg_kernel(const void* __restrict__ ei, const float* __restrict__ ea,
           const float* __restrict__ W1c, const float* __restrict__ b1,
           const float* __restrict__ W2, const float* __restrict__ b2) {
    __shared__ __align__(16) unsigned sB_hi[128 * 10];
    __shared__ __align__(16) unsigned sB_lo[128 * 10];
    __shared__ __align__(16) unsigned sH_hi[64 * 70];
    __shared__ __align__(16) unsigned sH_lo[64 * 70];
    __shared__ int s_src[64];
    __shared__ int s_tgt[64];

    int tid = threadIdx.x;
    int lane = tid & 31, wid = tid >> 5;
    int gid = lane >> 2, tig = lane & 3;
    int wm = wid & 3, wn = wid >> 2;
    int e0 = blockIdx.x * 64;

    int le = tid >> 2;
    int kq = tid & 3;
    int bn = tid & 127;
    int bkh = tid >> 7;

    int is64 = g_ei_is64;
    if (tid < 64) s_src[tid] = load_ei(ei, (size_t)e0 + tid, is64);
    else if (tid < 128) s_tgt[tid - 64] = load_ei(ei, (size_t)EE + e0 + (tid - 64), is64);

    float acc[8][4];
#pragma unroll
    for (int t = 0; t < 8; t++)
#pragma unroll
        for (int j = 0; j < 4; j++) acc[t][j] = 0.f;

    unsigned* sA_hi = sH_hi;
    unsigned* sA_lo = sH_lo;

    const int q0 = permp(2 * kq), q1 = permp(2 * kq + 1);
    const int arow0 = (wm * 16 + gid) * 10 + 2 * tig;

    __syncthreads();

    {
        const float* ap = ea + (size_t)(e0 + le) * 16 + kq * 4;
        float4 v = *(const float4*)ap;
        float w[8];
        const float* wp = W1c + (size_t)(bkh * 8) * HID + bn;
#pragma unroll
        for (int kk = 0; kk < 8; kk++) w[kk] = wp[(size_t)kk * HID];

        unsigned h0, l0, h1, l1;
        split2(v.x, v.y, h0, l0);
        split2(v.z, v.w, h1, l1);
        sA_hi[le * 10 + q0] = h0; sA_lo[le * 10 + q0] = l0;
        sA_hi[le * 10 + q1] = h1; sA_lo[le * 10 + q1] = l1;
#pragma unroll
        for (int j = 0; j < 4; j++) {
            unsigned hi, lo;
            split2(w[2 * j], w[2 * j + 1], hi, lo);
            int q = permp(bkh * 4 + j);
            sB_hi[bn * 10 + q] = hi;
            sB_lo[bn * 10 + q] = lo;
        }
        __syncthreads();

        uint2 AH0 = *(uint2*)&sA_hi[arow0];
        uint2 AH1 = *(uint2*)&sA_hi[arow0 + 80];
        uint2 AL0 = *(uint2*)&sA_lo[arow0];
        uint2 AL1 = *(uint2*)&sA_lo[arow0 + 80];
        unsigned ah[4] = {AH0.x, AH1.x, AH0.y, AH1.y};
        unsigned al[4] = {AL0.x, AL1.x, AL0.y, AL1.y};
#pragma unroll
        for (int t = 0; t < 8; t++) {
            int br = (wn * 64 + t * 8 + gid) * 10 + 2 * tig;
            uint2 BH = *(uint2*)&sB_hi[br];
            uint2 BL = *(uint2*)&sB_lo[br];
            unsigned bh[2] = {BH.x, BH.y};
            unsigned bl[2] = {BL.x, BL.y};
            MMA16816(acc[t], ah, bh);
            MMA16816(acc[t], ah, bl);
            MMA16816(acc[t], al, bh);
        }
    }

    __syncthreads();

    {
        int r0 = wm * 16 + gid;
        int n0t = s_tgt[r0], n0s = s_src[r0];
        int n1t = s_tgt[r0 + 8], n1s = s_src[r0 + 8];
        const float* P0 = g_P + (size_t)n0t * HID;
        const float* Q0 = g_Q + (size_t)n0s * HID;
        const float* P1 = g_P + (size_t)n1t * HID;
        const float* Q1 = g_Q + (size_t)n1s * HID;
#pragma unroll
        for (int t = 0; t < 8; t++) {
            int col = wn * 64 + t * 8 + tig * 2;
            float bb0 = b1[col], bb1 = b1[col + 1];
            float2 p0 = *(const float2*)(P0 + col);
            float2 qq0 = *(const float2*)(Q0 + col);
            float2 p1 = *(const float2*)(P1 + col);
            float2 qq1 = *(const float2*)(Q1 + col);
            float x0 = fmaxf(acc[t][0] + bb0 + p0.x + qq0.x, 0.f);
            float x1 = fmaxf(acc[t][1] + bb1 + p0.y + qq0.y, 0.f);
            float x2 = fmaxf(acc[t][2] + bb0 + p1.x + qq1.x, 0.f);
            float x3 = fmaxf(acc[t][3] + bb1 + p1.y + qq1.y, 0.f);
            int c2 = col >> 4;
            int q = permp((t & 1) * 4 + tig);
            unsigned hi0, lo0, hi1, lo1;
            split2(x0, x1, hi0, lo0);
            split2(x2, x3, hi1, lo1);
            sH_hi[r0 * 70 + c2 * 8 + q] = hi0;
            sH_lo[r0 * 70 + c2 * 8 + q] = lo0;
            sH_hi[(r0 + 8) * 70 + c2 * 8 + q] = hi1;
            sH_lo[(r0 + 8) * 70 + c2 * 8 + q] = lo1;
#pragma unroll
            for (int j = 0; j < 4; j++) acc[t][j] = 0.f;
        }
    }
    __syncthreads();

    for (int c = 0; c < 8; c++) {
        float w[8];
        const float* wp = W2 + (size_t)(c * 16 + bkh * 8) * HID + bn;
#pragma unroll
        for (int kk = 0; kk < 8; kk++) w[kk] = wp[(size_t)kk * HID];
        __syncthreads();
#pragma unroll
        for (int j = 0; j < 4; j++) {
            unsigned hi, lo;
            split2(w[2 * j], w[2 * j + 1], hi, lo);
            int q = permp(bkh * 4 + j);
            sB_hi[bn * 10 + q] = hi;
            sB_lo[bn * 10 + q] = lo;
        }
        __syncthreads();

        int ar = (wm * 16 + gid) * 70 + c * 8 + 2 * tig;
        uint2 AH0 = *(uint2*)&sH_hi[ar];
        uint2 AH1 = *(uint2*)&sH_hi[ar + 560];
        uint2 AL0 = *(uint2*)&sH_lo[ar];
        uint2 AL1 = *(uint2*)&sH_lo[ar + 560];
        unsigned ah[4] = {AH0.x, AH1.x, AH0.y, AH1.y};
        unsigned al[4] = {AL0.x, AL1.x, AL0.y, AL1.y};
#pragma unroll
        for (int t = 0; t < 8; t++) {
            int br = (wn * 64 + t * 8 + gid) * 10 + 2 * tig;
            uint2 BH = *(uint2*)&sB_hi[br];
            uint2 BL = *(uint2*)&sB_lo[br];
            unsigned bh[2] = {BH.x, BH.y};
            unsigned bl[2] = {BL.x, BL.y};
            MMA16816(acc[t], ah, bh);
            MMA16816(acc[t], ah, bl);
            MMA16816(acc[t], al, bh);
        }
    }

    {
        int r0 = wm * 16 + gid;
        int n0 = s_tgt[r0], n1 = s_tgt[r0 + 8];
#pragma unroll
        for (int t = 0; t < 8; t++) {
            int col = wn * 64 + t * 8 + tig * 2;
            float bb0 = b2[col], bb1 = b2[col + 1];
            RED2(g_aggr + (size_t)n0 * HID + col, acc[t][0] + bb0, acc[t][1] + bb1);
            RED2(g_aggr + (size_t)n1 * HID + col, acc[t][2] + bb0, acc[t][3] + bb1);
        }
    }
}

// ---------------------------------------------------------------------------
// Update kernel (mma): per 64-node tile:
//   hidden = ReLU([h | aggr*rdeg] @ W1 + b1)  K=256 (16 panels)
//   out = hidden @ W2 + b2                    K=128 (8 panels)
//   h = LN(h + out)
// ---------------------------------------------------------------------------
__global__ void __launch_bounds__(256)
upd_kernel(const float* __restrict__ W1, const float* __restrict__ b1,
           const float* __restrict__ W2, const float* __restrict__ b2,
           const float* __restrict__ lng, const float* __restrict__ lnb) {
    __shared__ __align__(16) unsigned sB_hi[128 * 10];
    __shared__ __align__(16) unsigned sB_lo[128 * 10];
    __shared__ __align__(16) unsigned sHbuf[2 * 64 * 70];  // sH_hi | sH_lo; also sF
    unsigned* sH_hi = sHbuf;
    unsigned* sH_lo = sHbuf + 64 * 70;
    float* sF = (float*)sHbuf;                              // [64][132] (epi2/LN)

    int tid = threadIdx.x;
    int lane = tid & 31, wid = tid >> 5;
    int gid = lane >> 2, tig = lane & 3;
    int wm = wid & 3, wn = wid >> 2;
    int n0 = blockIdx.x * 64;

    int le = tid >> 2, kq = tid & 3;
    int bn = tid & 127, bkh = tid >> 7;
    int lnode = min(n0 + le, NN - 1);
    float rd = g_rdeg[lnode];

    unsigned* sA_hi = sH_hi;   // alias during GEMM1 ([64][10] region)
    unsigned* sA_lo = sH_lo;

    const int q0 = permp(2 * kq), q1 = permp(2 * kq + 1);
    const int arow0 = (wm * 16 + gid) * 10 + 2 * tig;

    float acc[8][4];
#pragma unroll
    for (int t = 0; t < 8; t++)
#pragma unroll
        for (int j = 0; j < 4; j++) acc[t][j] = 0.f;

    // ---- GEMM1: K=256, 16 panels ----
    for (int c = 0; c < 16; c++) {
        const float* ap = (c < 8) ? g_h + (size_t)lnode * HID + c * 16 + kq * 4
                                  : g_aggr + (size_t)lnode * HID + (c - 8) * 16 + kq * 4;
        float4 v = *(const float4*)ap;
        if (c >= 8) { v.x *= rd; v.y *= rd; v.z *= rd; v.w *= rd; }
        float w[8];
        const float* wp = W1 + (size_t)(c * 16 + bkh * 8) * HID + bn;
#pragma unroll
        for (int kk = 0; kk < 8; kk++) w[kk] = wp[(size_t)kk * HID];
        __syncthreads();  // prev panel mma reads done
        unsigned h0, l0, h1, l1;
        split2(v.x, v.y, h0, l0);
        split2(v.z, v.w, h1, l1);
        sA_hi[le * 10 + q0] = h0; sA_lo[le * 10 + q0] = l0;
        sA_hi[le * 10 + q1] = h1; sA_lo[le * 10 + q1] = l1;
#pragma unroll
        for (int j = 0; j < 4; j++) {
            unsigned hi, lo;
            split2(w[2 * j], w[2 * j + 1], hi, lo);
            int q = permp(bkh * 4 + j);
            sB_hi[bn * 10 + q] = hi;
            sB_lo[bn * 10 + q] = lo;
        }
        __syncthreads();
        uint2 AH0 = *(uint2*)&sA_hi[arow0];
        uint2 AH1 = *(uint2*)&sA_hi[arow0 + 80];
        uint2 AL0 = *(uint2*)&sA_lo[arow0];
        uint2 AL1 = *(uint2*)&sA_lo[arow0 + 80];
        unsigned ah[4] = {AH0.x, AH1.x, AH0.y, AH1.y};
        unsigned al[4] = {AL0.x, AL1.x, AL0.y, AL1.y};
#pragma unroll
        for (int t = 0; t < 8; t++) {
            int br = (wn * 64 + t * 8 + gid) * 10 + 2 * tig;
            uint2 BH = *(uint2*)&sB_hi[br];
            uint2 BL = *(uint2*)&sB_lo[br];
            unsigned bh[2] = {BH.x, BH.y};
            unsigned bl[2] = {BL.x, BL.y};
            MMA16816(acc[t], ah, bh);
            MMA16816(acc[t], ah, bl);
            MMA16816(acc[t], al, bh);
        }
    }
    __syncthreads();  // all GEMM1 mma done before sH overwrite

    // ---- epi1: bias + ReLU -> sH fragments ----
    {
        int r0 = wm * 16 + gid;
#pragma unroll
        for (int t = 0; t < 8; t++) {
            int col = wn * 64 + t * 8 + tig * 2;
            float bb0 = b1[col], bb1 = b1[col + 1];
            float x0 = fmaxf(acc[t][0] + bb0, 0.f);
            float x1 = fmaxf(acc[t][1] + bb1, 0.f);
            float x2 = fmaxf(acc[t][2] + bb0, 0.f);
            float x3 = fmaxf(acc[t][3] + bb1, 0.f);
            int c2 = col >> 4;
            int q = permp((t & 1) * 4 + tig);
            unsigned hi0, lo0, hi1, lo1;
            split2(x0, x1, hi0, lo0);
            split2(x2, x3, hi1, lo1);
            sH_hi[r0 * 70 + c2 * 8 + q] = hi0;
            sH_lo[r0 * 70 + c2 * 8 + q] = lo0;
            sH_hi[(r0 + 8) * 70 + c2 * 8 + q] = hi1;
            sH_lo[(r0 + 8) * 70 + c2 * 8 + q] = lo1;
#pragma unroll
            for (int j = 0; j < 4; j++) acc[t][j] = 0.f;
        }
    }
    __syncthreads();

    // ---- GEMM2: K=128, 8 panels ----
    for (int c = 0; c < 8; c++) {
        float w[8];
        const float* wp = W2 + (size_t)(c * 16 + bkh * 8) * HID + bn;
#pragma unroll
        for (int kk = 0; kk < 8; kk++) w[kk] = wp[(size_t)kk * HID];
        __syncthreads();
#pragma unroll
        for (int j = 0; j < 4; j++) {
            unsigned hi, lo;
            split2(w[2 * j], w[2 * j + 1], hi, lo);
            int q = permp(bkh * 4 + j);
            sB_hi[bn * 10 + q] = hi;
            sB_lo[bn * 10 + q] = lo;
        }
        __syncthreads();
        int ar = (wm * 16 + gid) * 70 + c * 8 + 2 * tig;
        uint2 AH0 = *(uint2*)&sH_hi[ar];
        uint2 AH1 = *(uint2*)&sH_hi[ar + 560];
        uint2 AL0 = *(uint2*)&sH_lo[ar];
        uint2 AL1 = *(uint2*)&sH_lo[ar + 560];
        unsigned ah[4] = {AH0.x, AH1.x, AH0.y, AH1.y};
        unsigned al[4] = {AL0.x, AL1.x, AL0.y, AL1.y};
#pragma unroll
        for (int t = 0; t < 8; t++) {
            int br = (wn * 64 + t * 8 + gid) * 10 + 2 * tig;
            uint2 BH = *(uint2*)&sB_hi[br];
            uint2 BL = *(uint2*)&sB_lo[br];
            unsigned bh[2] = {BH.x, BH.y};
            unsigned bl[2] = {BL.x, BL.y};
            MMA16816(acc[t], ah, bh);
            MMA16816(acc[t], ah, bl);
            MMA16816(acc[t], al, bh);
        }
    }
    __syncthreads();  // all GEMM2 mma done before sF overwrite of sH

    // ---- epi2: +b2 + residual -> sF ----
    {
        int r0 = wm * 16 + gid;
        int node0 = min(n0 + r0, NN - 1), node1 = min(n0 + r0 + 8, NN - 1);
        const float* h0p = g_h + (size_t)node0 * HID;
        const float* h1p = g_h + (size_t)node1 * HID;
#pragma unroll
        for (int t = 0; t < 8; t++) {
            int col = wn * 64 + t * 8 + tig * 2;
            float bb0 = b2[col], bb1 = b2[col + 1];
            float2 ho0 = *(const float2*)(h0p + col);
            float2 ho1 = *(const float2*)(h1p + col);
            *(float2*)(sF + r0 * 132 + col) =
                make_float2(acc[t][0] + bb0 + ho0.x, acc[t][1] + bb1 + ho0.y);
            *(float2*)(sF + (r0 + 8) * 132 + col) =
                make_float2(acc[t][2] + bb0 + ho1.x, acc[t][3] + bb1 + ho1.y);
        }
    }
    __syncthreads();

    // ---- LayerNorm per row, write h ----
    {
        int w = tid >> 5;
        for (int r = w; r < 64; r += 8) {
            int node = n0 + r;
            float4 v = *(float4*)(sF + r * 132 + lane * 4);
            float s = v.x + v.y + v.z + v.w;
            float sq = fmaf(v.x, v.x, fmaf(v.y, v.y, fmaf(v.z, v.z, v.w * v.w)));
#pragma unroll
            for (int o = 16; o; o >>= 1) {
                s += __shfl_xor_sync(0xffffffffu, s, o);
                sq += __shfl_xor_sync(0xffffffffu, sq, o);
            }
            float mu = s * (1.f / HID);
            float var = sq * (1.f / HID) - mu * mu;
            float rstd = rsqrtf(var + 1e-5f);
            if (node < NN) {
                int cc = lane * 4;
                float4 o;
                o.x = (v.x - mu) * rstd * lng[cc + 0] + lnb[cc + 0];
                o.y = (v.y - mu) * rstd * lng[cc + 1] + lnb[cc + 1];
                o.z = (v.z - mu) * rstd * lng[cc + 2] + lnb[cc + 2];
                o.w = (v.w - mu) * rstd * lng[cc + 3] + lnb[cc + 3];
                *(float4*)(g_h + (size_t)node * HID + cc) = o;
            }
        }
    }
}

// ---------------------------------------------------------------------------
// Head kernel (mma): out = h @ head_W + head_b   (K=128)
// ---------------------------------------------------------------------------
__global__ void __launch_bounds__(256)
head_kernel(const float* __restrict__ W, const float* __restrict__ b,
            float* __restrict__ out) {
    __shared__ __align__(16) unsigned sB_hi[128 * 10];
    __shared__ __align__(16) unsigned sB_lo[128 * 10];
    __shared__ __align__(16) unsigned sA_hi[64 * 10];
    __shared__ __align__(16) unsigned sA_lo[64 * 10];

    int tid = threadIdx.x;
    int lane = tid & 31, wid = tid >> 5;
    int gid = lane >> 2, tig = lane & 3;
    int wm = wid & 3, wn = wid >> 2;
    int n0 = blockIdx.x * 64;

    int le = tid >> 2, kq = tid & 3;
    int bn = tid & 127, bkh = tid >> 7;
    int lnode = min(n0 + le, NN - 1);

    const int q0 = permp(2 * kq), q1 = permp(2 * kq + 1);
    const int arow0 = (wm * 16 + gid) * 10 + 2 * tig;

    float acc[8][4];
#pragma unroll
    for (int t = 0; t < 8; t++)
#pragma unroll
        for (int j = 0; j < 4; j++) acc[t][j] = 0.f;

    for (int c = 0; c < 8; c++) {
        float4 v = *(const float4*)(g_h + (size_t)lnode * HID + c * 16 + kq * 4);
        float w[8];
        const float* wp = W + (size_t)(c * 16 + bkh * 8) * HID + bn;
#pragma unroll
        for (int kk = 0; kk < 8; kk++) w[kk] = wp[(size_t)kk * HID];
        __syncthreads();
        unsigned h0, l0, h1, l1;
        split2(v.x, v.y, h0, l0);
        split2(v.z, v.w, h1, l1);
        sA_hi[le * 10 + q0] = h0; sA_lo[le * 10 + q0] = l0;
        sA_hi[le * 10 + q1] = h1; sA_lo[le * 10 + q1] = l1;
#pragma unroll
        for (int j = 0; j < 4; j++) {
            unsigned hi, lo;
            split2(w[2 * j], w[2 * j + 1], hi, lo);
            int q = permp(bkh * 4 + j);
            sB_hi[bn * 10 + q] = hi;
            sB_lo[bn * 10 + q] = lo;
        }
        __syncthreads();
        uint2 AH0 = *(uint2*)&sA_hi[arow0];
        uint2 AH1 = *(uint2*)&sA_hi[arow0 + 80];
        uint2 AL0 = *(uint2*)&sA_lo[arow0];
        uint2 AL1 = *(uint2*)&sA_lo[arow0 + 80];
        unsigned ah[4] = {AH0.x, AH1.x, AH0.y, AH1.y};
        unsigned al[4] = {AL0.x, AL1.x, AL0.y, AL1.y};
#pragma unroll
        for (int t = 0; t < 8; t++) {
            int br = (wn * 64 + t * 8 + gid) * 10 + 2 * tig;
            uint2 BH = *(uint2*)&sB_hi[br];
            uint2 BL = *(uint2*)&sB_lo[br];
            unsigned bh[2] = {BH.x, BH.y};
            unsigned bl[2] = {BL.x, BL.y};
            MMA16816(acc[t], ah, bh);
            MMA16816(acc[t], ah, bl);
            MMA16816(acc[t], al, bh);
        }
    }

    int r0 = wm * 16 + gid;
    int node0 = n0 + r0, node1 = n0 + r0 + 8;
#pragma unroll
    for (int t = 0; t < 8; t++) {
        int col = wn * 64 + t * 8 + tig * 2;
        float bb0 = b[col], bb1 = b[col + 1];
        if (node0 < NN) *(float2*)(out + (size_t)node0 * HID + col) =
            make_float2(acc[t][0] + bb0, acc[t][1] + bb1);
        if (node1 < NN) *(float2*)(out + (size_t)node1 * HID + col) =
            make_float2(acc[t][2] + bb0, acc[t][3] + bb1);
    }
}

// ---------------------------------------------------------------------------
extern "C" void kernel_launch(void* const* d_in, const int* in_sizes, int n_in,
                              void* d_out, int out_size) {
    const float* x = (const float*)d_in[0];
    const void* ei = d_in[1];
    const float* ea = (const float*)d_in[2];
    const float* enc_W = (const float*)d_in[3];
    const float* enc_b = (const float*)d_in[4];
    const float* enc_g = (const float*)d_in[5];
    const float* enc_beta = (const float*)d_in[6];
    const float* msg_W1 = (const float*)d_in[7];
    const float* msg_b1 = (const float*)d_in[8];
    const float* msg_W2 = (const float*)d_in[9];
    const float* msg_b2 = (const float*)d_in[10];
    const float* upd_W1 = (const float*)d_in[11];
    const float* upd_b1 = (const float*)d_in[12];
    const float* upd_W2 = (const float*)d_in[13];
    const float* upd_b2 = (const float*)d_in[14];
    const float* ln_g = (const float*)d_in[15];
    const float* ln_beta = (const float*)d_in[16];
    const float* head_W = (const float*)d_in[17];
    const float* head_b = (const float*)d_in[18];
    float* out = (float*)d_out;

    static float* dP = nullptr;
    static float* dQ = nullptr;
    if (!dP) {
        cudaGetSymbolAddress((void**)&dP, g_P);
        cudaGetSymbolAddress((void**)&dQ, g_Q);
    }

    const int NB = (NN + 63) / 64;
    const int ZB = ((size_t)NN * HID + 255) / 256;

    // ---- layer 0; msg at launch index 3 so ncu profiles it ----
    init_aggr_kernel<<<ZB, 256>>>((const unsigned*)ei);
    enc_kernel<<<NN, 128>>>(x, enc_W, enc_b, enc_g, enc_beta);
    nodemm2_kernel<<<dim3(NB, 2), 256>>>(msg_W1, dP, dQ);
    msg_kernel<<<EE / 64, 256>>>(
        ei, ea,
        msg_W1 + (size_t)256 * HID, msg_b1,
        msg_W2, msg_b2);
    zero_deg_kernel<<<(NN + 255) / 256, 256>>>();
    deg_kernel<<<(EE + 255) / 256, 256>>>(ei);
    rdeg_kernel<<<(NN + 255) / 256, 256>>>();
    upd_kernel<<<NB, 256>>>(
        upd_W1, upd_b1, upd_W2, upd_b2, ln_g, ln_beta);

    // ---- layer 1 ----
    const float* W1_1 = msg_W1 + (size_t)272 * HID;
    nodemm2_kernel<<<dim3(NB, 2), 256>>>(W1_1, dP, dQ);
    init_aggr_kernel<<<ZB, 256>>>((const unsigned*)ei);
    msg_kernel<<<EE / 64, 256>>>(
        ei, ea,
        W1_1 + (size_t)256 * HID, msg_b1 + HID,
        msg_W2 + (size_t)HID * HID, msg_b2 + HID);
    upd_kernel<<<NB, 256>>>(
        upd_W1 + (size_t)256 * HID, upd_b1 + HID,
        upd_W2 + (size_t)HID * HID, upd_b2 + HID,
        ln_g + HID, ln_beta + HID);

    head_kernel<<<NB, 256>>>(head_W, head_b, out);
}

// round 14
// speedup vs baseline: 1.2957x; 1.0138x over previous
#include <cuda_runtime.h>
#include <cuda_bf16.h>
#include <cstdint>

#define NN 50000
#define EE 800000
#define HID 128

// Scratch (device globals — no allocation allowed)
__device__ float g_h[(size_t)NN * HID];
__device__ float g_aggr[(size_t)NN * HID];
__device__ float g_P[(size_t)NN * HID];
__device__ float g_Q[(size_t)NN * HID];
__device__ float g_rdeg[NN];
__device__ int g_ei_is64;

typedef unsigned long long u64;

#define RED2(ptr, a, b) \
    asm volatile("red.global.add.v2.f32 [%0], {%1, %2};" \
                 :: "l"(ptr), "f"(a), "f"(b) : "memory")

#define MMA16816(cc, aa, bb) \
    asm volatile("mma.sync.aligned.m16n8k16.row.col.f32.bf16.bf16.f32 " \
                 "{%0,%1,%2,%3}, {%4,%5,%6,%7}, {%8,%9}, {%0,%1,%2,%3};" \
                 : "+f"(cc[0]), "+f"(cc[1]), "+f"(cc[2]), "+f"(cc[3]) \
                 : "r"(aa[0]), "r"(aa[1]), "r"(aa[2]), "r"(aa[3]), \
                   "r"(bb[0]), "r"(bb[1]))

// split float pair into bf16 hi-pack and bf16 residual-pack (x in low bits)
__device__ __forceinline__ void split2(float x, float y, unsigned& hi, unsigned& lo) {
    __nv_bfloat16 xh = __float2bfloat16_rn(x);
    __nv_bfloat16 yh = __float2bfloat16_rn(y);
    __nv_bfloat16 xl = __float2bfloat16_rn(x - __bfloat162float(xh));
    __nv_bfloat16 yl = __float2bfloat16_rn(y - __bfloat162float(yh));
    hi = ((unsigned)__bfloat16_as_ushort(yh) << 16) | __bfloat16_as_ushort(xh);
    lo = ((unsigned)__bfloat16_as_ushort(yl) << 16) | __bfloat16_as_ushort(xl);
}

// perm: k-pair p (0..7) -> u32 slot so that (tig, tig+4) are adjacent
__device__ __forceinline__ int permp(int p) { return 2 * (p & 3) + (p >> 2); }

__device__ __forceinline__ int load_ei(const void* ei, size_t idx, int is64) {
    int v = is64 ? (int)((const long long*)ei)[idx] : ((const int*)ei)[idx];
    return min(max(v, 0), NN - 1);
}

// ---------------------------------------------------------------------------
__global__ void init_aggr_kernel(const unsigned* __restrict__ raw) {
    size_t i = (size_t)blockIdx.x * blockDim.x + threadIdx.x;
    if (i < (size_t)NN * HID) g_aggr[i] = 0.f;
    if (blockIdx.x == 0 && threadIdx.x == 0) {
        int is64 = 1;
        for (int k = 0; k < 64; k++)
            if (raw[2 * k + 1] != 0u) { is64 = 0; break; }
        g_ei_is64 = is64;
    }
}

// ---------------------------------------------------------------------------
__global__ void enc_kernel(const float* __restrict__ x, const float* __restrict__ W,
                           const float* __restrict__ b, const float* __restrict__ g,
                           const float* __restrict__ beta) {
    int node = blockIdx.x;
    int t = threadIdx.x;
    __shared__ float sx[32];
    __shared__ float red[8];
    if (t < 32) sx[t] = x[node * 32 + t];
    __syncthreads();
    float acc = b[t];
#pragma unroll
    for (int k = 0; k < 32; k++) acc = fmaf(sx[k], W[k * HID + t], acc);
    acc = fmaxf(acc, 0.f);
    float s = acc, sq = acc * acc;
#pragma unroll
    for (int o = 16; o; o >>= 1) {
        s += __shfl_xor_sync(0xffffffffu, s, o);
        sq += __shfl_xor_sync(0xffffffffu, sq, o);
    }
    int w = t >> 5;
    if ((t & 31) == 0) { red[w] = s; red[4 + w] = sq; }
    __syncthreads();
    s = red[0] + red[1] + red[2] + red[3];
    sq = red[4] + red[5] + red[6] + red[7];
    float mu = s * (1.f / HID);
    float var = sq * (1.f / HID) - mu * mu;
    g_h[(size_t)node * HID + t] = (acc - mu) * rsqrtf(var + 1e-5f) * g[t] + beta[t];
}

__global__ void zero_deg_kernel() {
    int i = blockIdx.x * blockDim.x + threadIdx.x;
    if (i < NN) g_rdeg[i] = 0.f;
}
__global__ void deg_kernel(const void* __restrict__ ei) {
    int e = blockIdx.x * blockDim.x + threadIdx.x;
    int is64 = g_ei_is64;
    if (e < EE) atomicAdd(&g_rdeg[load_ei(ei, (size_t)EE + e, is64)], 1.f);
}
__global__ void rdeg_kernel() {
    int i = blockIdx.x * blockDim.x + threadIdx.x;
    if (i < NN) g_rdeg[i] = 1.f / fmaxf(g_rdeg[i], 1.f);
}

// ---------------------------------------------------------------------------
// Node GEMM (mma): blockIdx.y: 0 -> P = h@W1[0:128], 1 -> Q = h@W1[128:256]
// (unchanged from R13, validated)
// ---------------------------------------------------------------------------
__global__ void __launch_bounds__(256)
nodemm2_kernel(const float* __restrict__ W1, float* __restrict__ P, float* __restrict__ Q) {
    __shared__ __align__(16) unsigned sB_hi[128 * 10];
    __shared__ __align__(16) unsigned sB_lo[128 * 10];
    __shared__ __align__(16) unsigned sA_hi[64 * 10];
    __shared__ __align__(16) unsigned sA_lo[64 * 10];

    const float* W = W1 + (size_t)blockIdx.y * 128 * HID;
    float* out = blockIdx.y ? Q : P;

    int tid = threadIdx.x;
    int lane = tid & 31, wid = tid >> 5;
    int gid = lane >> 2, tig = lane & 3;
    int wm = wid & 3, wn = wid >> 2;
    int n0 = blockIdx.x * 64;

    int le = tid >> 2, kq = tid & 3;
    int bn = tid & 127, bkh = tid >> 7;
    int lnode = min(n0 + le, NN - 1);

    const int q0 = permp(2 * kq), q1 = permp(2 * kq + 1);
    const int arow0 = (wm * 16 + gid) * 10 + 2 * tig;

    float acc[8][4];
#pragma unroll
    for (int t = 0; t < 8; t++)
#pragma unroll
        for (int j = 0; j < 4; j++) acc[t][j] = 0.f;

    for (int c = 0; c < 8; c++) {
        float4 v = *(const float4*)(g_h + (size_t)lnode * HID + c * 16 + kq * 4);
        float w[8];
        const float* wp = W + (size_t)(c * 16 + bkh * 8) * HID + bn;
#pragma unroll
        for (int kk = 0; kk < 8; kk++) w[kk] = wp[(size_t)kk * HID];
        __syncthreads();
        unsigned h0, l0, h1, l1;
        split2(v.x, v.y, h0, l0);
        split2(v.z, v.w, h1, l1);
        sA_hi[le * 10 + q0] = h0; sA_lo[le * 10 + q0] = l0;
        sA_hi[le * 10 + q1] = h1; sA_lo[le * 10 + q1] = l1;
#pragma unroll
        for (int j = 0; j < 4; j++) {
            unsigned hi, lo;
            split2(w[2 * j], w[2 * j + 1], hi, lo);
            int q = permp(bkh * 4 + j);
            sB_hi[bn * 10 + q] = hi;
            sB_lo[bn * 10 + q] = lo;
        }
        __syncthreads();
        uint2 AH0 = *(uint2*)&sA_hi[arow0];
        uint2 AH1 = *(uint2*)&sA_hi[arow0 + 80];
        uint2 AL0 = *(uint2*)&sA_lo[arow0];
        uint2 AL1 = *(uint2*)&sA_lo[arow0 + 80];
        unsigned ah[4] = {AH0.x, AH1.x, AH0.y, AH1.y};
        unsigned al[4] = {AL0.x, AL1.x, AL0.y, AL1.y};
#pragma unroll
        for (int t = 0; t < 8; t++) {
            int br = (wn * 64 + t * 8 + gid) * 10 + 2 * tig;
            uint2 BH = *(uint2*)&sB_hi[br];
            uint2 BL = *(uint2*)&sB_lo[br];
            unsigned bh[2] = {BH.x, BH.y};
            unsigned bl[2] = {BL.x, BL.y};
            MMA16816(acc[t], ah, bh);
            MMA16816(acc[t], ah, bl);
            MMA16816(acc[t], al, bh);
        }
    }

    int r0 = wm * 16 + gid;
    int node0 = n0 + r0, node1 = n0 + r0 + 8;
#pragma unroll
    for (int t = 0; t < 8; t++) {
        int col = wn * 64 + t * 8 + tig * 2;
        if (node0 < NN) *(float2*)(out + (size_t)node0 * HID + col) = make_float2(acc[t][0], acc[t][1]);
        if (node1 < NN) *(float2*)(out + (size_t)node1 * HID + col) = make_float2(acc[t][2], acc[t][3]);
    }
}

// ---------------------------------------------------------------------------
// Message kernel — 2(M)x4(N) warp grid (halves B-fragment LDS replication):
//   each warp: 32 rows (2 m16 tiles) x 32 cols (4 n8 tiles)
// Algebra identical to R13 msg; only warp->tile mapping changed.
// ---------------------------------------------------------------------------
__global__ void __launch_bounds__(256)
msg_kernel(const void* __restrict__ ei, const float* __restrict__ ea,
           const float* __restrict__ W1c, const float* __restrict__ b1,
           const float* __restrict__ W2, const float* __restrict__ b2) {
    __shared__ __align__(16) unsigned sB_hi[128 * 10];
    __shared__ __align__(16) unsigned sB_lo[128 * 10];
    __shared__ __align__(16) unsigned sH_hi[64 * 70];
    __shared__ __align__(16) unsigned sH_lo[64 * 70];
    __shared__ int s_src[64];
    __shared__ int s_tgt[64];

    int tid = threadIdx.x;
    int lane = tid & 31, wid = tid >> 5;
    int gid = lane >> 2, tig = lane & 3;
    int wm = wid >> 2;        // 0..1 : 32-row half
    int wn = wid & 3;         // 0..3 : 32-col group
    int e0 = blockIdx.x * 64;

    int le = tid >> 2;
    int kq = tid & 3;
    int bn = tid & 127;
    int bkh = tid >> 7;

    int is64 = g_ei_is64;
    if (tid < 64) s_src[tid] = load_ei(ei, (size_t)e0 + tid, is64);
    else if (tid < 128) s_tgt[tid - 64] = load_ei(ei, (size_t)EE + e0 + (tid - 64), is64);

    float acc[2][4][4];
#pragma unroll
    for (int mt = 0; mt < 2; mt++)
#pragma unroll
        for (int t = 0; t < 4; t++)
#pragma unroll
            for (int j = 0; j < 4; j++) acc[mt][t][j] = 0.f;

    unsigned* sA_hi = sH_hi;
    unsigned* sA_lo = sH_lo;

    const int q0 = permp(2 * kq), q1 = permp(2 * kq + 1);
    const int rr0 = wm * 32 + gid;       // m-tile 0 base row
    const int rr1 = wm * 32 + 16 + gid;  // m-tile 1 base row

    __syncthreads();

    // ================= GEMM1: single K=16 panel (ea @ W1c) =================
    {
        const float* ap = ea + (size_t)(e0 + le) * 16 + kq * 4;
        float4 v = *(const float4*)ap;
        float w[8];
        const float* wp = W1c + (size_t)(bkh * 8) * HID + bn;
#pragma unroll
        for (int kk = 0; kk < 8; kk++) w[kk] = wp[(size_t)kk * HID];

        unsigned h0, l0, h1, l1;
        split2(v.x, v.y, h0, l0);
        split2(v.z, v.w, h1, l1);
        sA_hi[le * 10 + q0] = h0; sA_lo[le * 10 + q0] = l0;
        sA_hi[le * 10 + q1] = h1; sA_lo[le * 10 + q1] = l1;
#pragma unroll
        for (int j = 0; j < 4; j++) {
            unsigned hi, lo;
            split2(w[2 * j], w[2 * j + 1], hi, lo);
            int q = permp(bkh * 4 + j);
            sB_hi[bn * 10 + q] = hi;
            sB_lo[bn * 10 + q] = lo;
        }
        __syncthreads();

        unsigned ah[2][4], al[2][4];
#pragma unroll
        for (int mt = 0; mt < 2; mt++) {
            int a0 = (wm * 32 + mt * 16 + gid) * 10 + 2 * tig;
            uint2 AH0 = *(uint2*)&sA_hi[a0];
            uint2 AH1 = *(uint2*)&sA_hi[a0 + 80];
            uint2 AL0 = *(uint2*)&sA_lo[a0];
            uint2 AL1 = *(uint2*)&sA_lo[a0 + 80];
            ah[mt][0] = AH0.x; ah[mt][1] = AH1.x; ah[mt][2] = AH0.y; ah[mt][3] = AH1.y;
            al[mt][0] = AL0.x; al[mt][1] = AL1.x; al[mt][2] = AL0.y; al[mt][3] = AL1.y;
        }
#pragma unroll
        for (int t = 0; t < 4; t++) {
            int br = (wn * 32 + t * 8 + gid) * 10 + 2 * tig;
            uint2 BH = *(uint2*)&sB_hi[br];
            uint2 BL = *(uint2*)&sB_lo[br];
            unsigned bh[2] = {BH.x, BH.y};
            unsigned bl[2] = {BL.x, BL.y};
#pragma unroll
            for (int mt = 0; mt < 2; mt++) {
                MMA16816(acc[mt][t], ah[mt], bh);
                MMA16816(acc[mt][t], ah[mt], bl);
                MMA16816(acc[mt][t], al[mt], bh);
            }
        }
    }

    __syncthreads();  // GEMM1 mma reads done before sH overwrite

    // ---- += P[tgt] + Q[src] + b1, ReLU -> sH fragments ----
#pragma unroll
    for (int mt = 0; mt < 2; mt++) {
        int r0 = (mt ? rr1 : rr0);
        int n0t = s_tgt[r0], n0s = s_src[r0];
        int n1t = s_tgt[r0 + 8], n1s = s_src[r0 + 8];
        const float* P0 = g_P + (size_t)n0t * HID;
        const float* Q0 = g_Q + (size_t)n0s * HID;
        const float* P1 = g_P + (size_t)n1t * HID;
        const float* Q1 = g_Q + (size_t)n1s * HID;
#pragma unroll
        for (int t = 0; t < 4; t++) {
            int col = wn * 32 + t * 8 + tig * 2;
            float bb0 = b1[col], bb1 = b1[col + 1];
            float2 p0 = *(const float2*)(P0 + col);
            float2 qq0 = *(const float2*)(Q0 + col);
            float2 p1 = *(const float2*)(P1 + col);
            float2 qq1 = *(const float2*)(Q1 + col);
            float x0 = fmaxf(acc[mt][t][0] + bb0 + p0.x + qq0.x, 0.f);
            float x1 = fmaxf(acc[mt][t][1] + bb1 + p0.y + qq0.y, 0.f);
            float x2 = fmaxf(acc[mt][t][2] + bb0 + p1.x + qq1.x, 0.f);
            float x3 = fmaxf(acc[mt][t][3] + bb1 + p1.y + qq1.y, 0.f);
            int c2 = col >> 4;
            int q = permp((t & 1) * 4 + tig);
            unsigned hi0, lo0, hi1, lo1;
            split2(x0, x1, hi0, lo0);
            split2(x2, x3, hi1, lo1);
            sH_hi[r0 * 70 + c2 * 8 + q] = hi0;
            sH_lo[r0 * 70 + c2 * 8 + q] = lo0;
            sH_hi[(r0 + 8) * 70 + c2 * 8 + q] = hi1;
            sH_lo[(r0 + 8) * 70 + c2 * 8 + q] = lo1;
#pragma unroll
            for (int j = 0; j < 4; j++) acc[mt][t][j] = 0.f;
        }
    }
    __syncthreads();

    // ================= GEMM2: K=128, 8 panels =================
    for (int c = 0; c < 8; c++) {
        float w[8];
        const float* wp = W2 + (size_t)(c * 16 + bkh * 8) * HID + bn;
#pragma unroll
        for (int kk = 0; kk < 8; kk++) w[kk] = wp[(size_t)kk * HID];
        __syncthreads();
#pragma unroll
        for (int j = 0; j < 4; j++) {
            unsigned hi, lo;
            split2(w[2 * j], w[2 * j + 1], hi, lo);
            int q = permp(bkh * 4 + j);
            sB_hi[bn * 10 + q] = hi;
            sB_lo[bn * 10 + q] = lo;
        }
        __syncthreads();

        unsigned ah[2][4], al[2][4];
#pragma unroll
        for (int mt = 0; mt < 2; mt++) {
            int ar = (wm * 32 + mt * 16 + gid) * 70 + c * 8 + 2 * tig;
            uint2 AH0 = *(uint2*)&sH_hi[ar];
            uint2 AH1 = *(uint2*)&sH_hi[ar + 560];
            uint2 AL0 = *(uint2*)&sH_lo[ar];
            uint2 AL1 = *(uint2*)&sH_lo[ar + 560];
            ah[mt][0] = AH0.x; ah[mt][1] = AH1.x; ah[mt][2] = AH0.y; ah[mt][3] = AH1.y;
            al[mt][0] = AL0.x; al[mt][1] = AL1.x; al[mt][2] = AL0.y; al[mt][3] = AL1.y;
        }
#pragma unroll
        for (int t = 0; t < 4; t++) {
            int br = (wn * 32 + t * 8 + gid) * 10 + 2 * tig;
            uint2 BH = *(uint2*)&sB_hi[br];
            uint2 BL = *(uint2*)&sB_lo[br];
            unsigned bh[2] = {BH.x, BH.y};
            unsigned bl[2] = {BL.x, BL.y};
#pragma unroll
            for (int mt = 0; mt < 2; mt++) {
                MMA16816(acc[mt][t], ah[mt], bh);
                MMA16816(acc[mt][t], ah[mt], bl);
                MMA16816(acc[mt][t], al[mt], bh);
            }
        }
    }

    // ---- scatter: m + b2 -> g_aggr[tgt] ----
#pragma unroll
    for (int mt = 0; mt < 2; mt++) {
        int r0 = (mt ? rr1 : rr0);
        int n0 = s_tgt[r0], n1 = s_tgt[r0 + 8];
#pragma unroll
        for (int t = 0; t < 4; t++) {
            int col = wn * 32 + t * 8 + tig * 2;
            float bb0 = b2[col], bb1 = b2[col + 1];
            RED2(g_aggr + (size_t)n0 * HID + col, acc[mt][t][0] + bb0, acc[mt][t][1] + bb1);
            RED2(g_aggr + (size_t)n1 * HID + col, acc[mt][t][2] + bb0, acc[mt][t][3] + bb1);
        }
    }
}

// ---------------------------------------------------------------------------
// Update kernel (unchanged from R13, validated)
// ---------------------------------------------------------------------------
__global__ void __launch_bounds__(256)
upd_kernel(const float* __restrict__ W1, const float* __restrict__ b1,
           const float* __restrict__ W2, const float* __restrict__ b2,
           const float* __restrict__ lng, const float* __restrict__ lnb) {
    __shared__ __align__(16) unsigned sB_hi[128 * 10];
    __shared__ __align__(16) unsigned sB_lo[128 * 10];
    __shared__ __align__(16) unsigned sHbuf[2 * 64 * 70];
    unsigned* sH_hi = sHbuf;
    unsigned* sH_lo = sHbuf + 64 * 70;
    float* sF = (float*)sHbuf;

    int tid = threadIdx.x;
    int lane = tid & 31, wid = tid >> 5;
    int gid = lane >> 2, tig = lane & 3;
    int wm = wid & 3, wn = wid >> 2;
    int n0 = blockIdx.x * 64;

    int le = tid >> 2, kq = tid & 3;
    int bn = tid & 127, bkh = tid >> 7;
    int lnode = min(n0 + le, NN - 1);
    float rd = g_rdeg[lnode];

    unsigned* sA_hi = sH_hi;
    unsigned* sA_lo = sH_lo;

    const int q0 = permp(2 * kq), q1 = permp(2 * kq + 1);
    const int arow0 = (wm * 16 + gid) * 10 + 2 * tig;

    float acc[8][4];
#pragma unroll
    for (int t = 0; t < 8; t++)
#pragma unroll
        for (int j = 0; j < 4; j++) acc[t][j] = 0.f;

    for (int c = 0; c < 16; c++) {
        const float* ap = (c < 8) ? g_h + (size_t)lnode * HID + c * 16 + kq * 4
                                  : g_aggr + (size_t)lnode * HID + (c - 8) * 16 + kq * 4;
        float4 v = *(const float4*)ap;
        if (c >= 8) { v.x *= rd; v.y *= rd; v.z *= rd; v.w *= rd; }
        float w[8];
        const float* wp = W1 + (size_t)(c * 16 + bkh * 8) * HID + bn;
#pragma unroll
        for (int kk = 0; kk < 8; kk++) w[kk] = wp[(size_t)kk * HID];
        __syncthreads();
        unsigned h0, l0, h1, l1;
        split2(v.x, v.y, h0, l0);
        split2(v.z, v.w, h1, l1);
        sA_hi[le * 10 + q0] = h0; sA_lo[le * 10 + q0] = l0;
        sA_hi[le * 10 + q1] = h1; sA_lo[le * 10 + q1] = l1;
#pragma unroll
        for (int j = 0; j < 4; j++) {
            unsigned hi, lo;
            split2(w[2 * j], w[2 * j + 1], hi, lo);
            int q = permp(bkh * 4 + j);
            sB_hi[bn * 10 + q] = hi;
            sB_lo[bn * 10 + q] = lo;
        }
        __syncthreads();
        uint2 AH0 = *(uint2*)&sA_hi[arow0];
        uint2 AH1 = *(uint2*)&sA_hi[arow0 + 80];
        uint2 AL0 = *(uint2*)&sA_lo[arow0];
        uint2 AL1 = *(uint2*)&sA_lo[arow0 + 80];
        unsigned ah[4] = {AH0.x, AH1.x, AH0.y, AH1.y};
        unsigned al[4] = {AL0.x, AL1.x, AL0.y, AL1.y};
#pragma unroll
        for (int t = 0; t < 8; t++) {
            int br = (wn * 64 + t * 8 + gid) * 10 + 2 * tig;
            uint2 BH = *(uint2*)&sB_hi[br];
            uint2 BL = *(uint2*)&sB_lo[br];
            unsigned bh[2] = {BH.x, BH.y};
            unsigned bl[2] = {BL.x, BL.y};
            MMA16816(acc[t], ah, bh);
            MMA16816(acc[t], ah, bl);
            MMA16816(acc[t], al, bh);
        }
    }
    __syncthreads();

    {
        int r0 = wm * 16 + gid;
#pragma unroll
        for (int t = 0; t < 8; t++) {
            int col = wn * 64 + t * 8 + tig * 2;
            float bb0 = b1[col], bb1 = b1[col + 1];
            float x0 = fmaxf(acc[t][0] + bb0, 0.f);
            float x1 = fmaxf(acc[t][1] + bb1, 0.f);
            float x2 = fmaxf(acc[t][2] + bb0, 0.f);
            float x3 = fmaxf(acc[t][3] + bb1, 0.f);
            int c2 = col >> 4;
            int q = permp((t & 1) * 4 + tig);
            unsigned hi0, lo0, hi1, lo1;
            split2(x0, x1, hi0, lo0);
            split2(x2, x3, hi1, lo1);
            sH_hi[r0 * 70 + c2 * 8 + q] = hi0;
            sH_lo[r0 * 70 + c2 * 8 + q] = lo0;
            sH_hi[(r0 + 8) * 70 + c2 * 8 + q] = hi1;
            sH_lo[(r0 + 8) * 70 + c2 * 8 + q] = lo1;
#pragma unroll
            for (int j = 0; j < 4; j++) acc[t][j] = 0.f;
        }
    }
    __syncthreads();

    for (int c = 0; c < 8; c++) {
        float w[8];
        const float* wp = W2 + (size_t)(c * 16 + bkh * 8) * HID + bn;
#pragma unroll
        for (int kk = 0; kk < 8; kk++) w[kk] = wp[(size_t)kk * HID];
        __syncthreads();
#pragma unroll
        for (int j = 0; j < 4; j++) {
            unsigned hi, lo;
            split2(w[2 * j], w[2 * j + 1], hi, lo);
            int q = permp(bkh * 4 + j);
            sB_hi[bn * 10 + q] = hi;
            sB_lo[bn * 10 + q] = lo;
        }
        __syncthreads();
        int ar = (wm * 16 + gid) * 70 + c * 8 + 2 * tig;
        uint2 AH0 = *(uint2*)&sH_hi[ar];
        uint2 AH1 = *(uint2*)&sH_hi[ar + 560];
        uint2 AL0 = *(uint2*)&sH_lo[ar];
        uint2 AL1 = *(uint2*)&sH_lo[ar + 560];
        unsigned ah[4] = {AH0.x, AH1.x, AH0.y, AH1.y};
        unsigned al[4] = {AL0.x, AL1.x, AL0.y, AL1.y};
#pragma unroll
        for (int t = 0; t < 8; t++) {
            int br = (wn * 64 + t * 8 + gid) * 10 + 2 * tig;
            uint2 BH = *(uint2*)&sB_hi[br];
            uint2 BL = *(uint2*)&sB_lo[br];
            unsigned bh[2] = {BH.x, BH.y};
            unsigned bl[2] = {BL.x, BL.y};
            MMA16816(acc[t], ah, bh);
            MMA16816(acc[t], ah, bl);
            MMA16816(acc[t], al, bh);
        }
    }
    __syncthreads();

    {
        int r0 = wm * 16 + gid;
        int node0 = min(n0 + r0, NN - 1), node1 = min(n0 + r0 + 8, NN - 1);
        const float* h0p = g_h + (size_t)node0 * HID;
        const float* h1p = g_h + (size_t)node1 * HID;
#pragma unroll
        for (int t = 0; t < 8; t++) {
            int col = wn * 64 + t * 8 + tig * 2;
            float bb0 = b2[col], bb1 = b2[col + 1];
            float2 ho0 = *(const float2*)(h0p + col);
            float2 ho1 = *(const float2*)(h1p + col);
            *(float2*)(sF + r0 * 132 + col) =
                make_float2(acc[t][0] + bb0 + ho0.x, acc[t][1] + bb1 + ho0.y);
            *(float2*)(sF + (r0 + 8) * 132 + col) =
                make_float2(acc[t][2] + bb0 + ho1.x, acc[t][3] + bb1 + ho1.y);
        }
    }
    __syncthreads();

    {
        int w = tid >> 5;
        for (int r = w; r < 64; r += 8) {
            int node = n0 + r;
            float4 v = *(float4*)(sF + r * 132 + lane * 4);
            float s = v.x + v.y + v.z + v.w;
            float sq = fmaf(v.x, v.x, fmaf(v.y, v.y, fmaf(v.z, v.z, v.w * v.w)));
#pragma unroll
            for (int o = 16; o; o >>= 1) {
                s += __shfl_xor_sync(0xffffffffu, s, o);
                sq += __shfl_xor_sync(0xffffffffu, sq, o);
            }
            float mu = s * (1.f / HID);
            float var = sq * (1.f / HID) - mu * mu;
            float rstd = rsqrtf(var + 1e-5f);
            if (node < NN) {
                int cc = lane * 4;
                float4 o;
                o.x = (v.x - mu) * rstd * lng[cc + 0] + lnb[cc + 0];
                o.y = (v.y - mu) * rstd * lng[cc + 1] + lnb[cc + 1];
                o.z = (v.z - mu) * rstd * lng[cc + 2] + lnb[cc + 2];
                o.w = (v.w - mu) * rstd * lng[cc + 3] + lnb[cc + 3];
                *(float4*)(g_h + (size_t)node * HID + cc) = o;
            }
        }
    }
}

// ---------------------------------------------------------------------------
// Head kernel (unchanged from R13, validated)
// ---------------------------------------------------------------------------
__global__ void __launch_bounds__(256)
head_kernel(const float* __restrict__ W, const float* __restrict__ b,
            float* __restrict__ out) {
    __shared__ __align__(16) unsigned sB_hi[128 * 10];
    __shared__ __align__(16) unsigned sB_lo[128 * 10];
    __shared__ __align__(16) unsigned sA_hi[64 * 10];
    __shared__ __align__(16) unsigned sA_lo[64 * 10];

    int tid = threadIdx.x;
    int lane = tid & 31, wid = tid >> 5;
    int gid = lane >> 2, tig = lane & 3;
    int wm = wid & 3, wn = wid >> 2;
    int n0 = blockIdx.x * 64;

    int le = tid >> 2, kq = tid & 3;
    int bn = tid & 127, bkh = tid >> 7;
    int lnode = min(n0 + le, NN - 1);

    const int q0 = permp(2 * kq), q1 = permp(2 * kq + 1);
    const int arow0 = (wm * 16 + gid) * 10 + 2 * tig;

    float acc[8][4];
#pragma unroll
    for (int t = 0; t < 8; t++)
#pragma unroll
        for (int j = 0; j < 4; j++) acc[t][j] = 0.f;

    for (int c = 0; c < 8; c++) {
        float4 v = *(const float4*)(g_h + (size_t)lnode * HID + c * 16 + kq * 4);
        float w[8];
        const float* wp = W + (size_t)(c * 16 + bkh * 8) * HID + bn;
#pragma unroll
        for (int kk = 0; kk < 8; kk++) w[kk] = wp[(size_t)kk * HID];
        __syncthreads();
        unsigned h0, l0, h1, l1;
        split2(v.x, v.y, h0, l0);
        split2(v.z, v.w, h1, l1);
        sA_hi[le * 10 + q0] = h0; sA_lo[le * 10 + q0] = l0;
        sA_hi[le * 10 + q1] = h1; sA_lo[le * 10 + q1] = l1;
#pragma unroll
        for (int j = 0; j < 4; j++) {
            unsigned hi, lo;
            split2(w[2 * j], w[2 * j + 1], hi, lo);
            int q = permp(bkh * 4 + j);
            sB_hi[bn * 10 + q] = hi;
            sB_lo[bn * 10 + q] = lo;
        }
        __syncthreads();
        uint2 AH0 = *(uint2*)&sA_hi[arow0];
        uint2 AH1 = *(uint2*)&sA_hi[arow0 + 80];
        uint2 AL0 = *(uint2*)&sA_lo[arow0];
        uint2 AL1 = *(uint2*)&sA_lo[arow0 + 80];
        unsigned ah[4] = {AH0.x, AH1.x, AH0.y, AH1.y};
        unsigned al[4] = {AL0.x, AL1.x, AL0.y, AL1.y};
#pragma unroll
        for (int t = 0; t < 8; t++) {
            int br = (wn * 64 + t * 8 + gid) * 10 + 2 * tig;
            uint2 BH = *(uint2*)&sB_hi[br];
            uint2 BL = *(uint2*)&sB_lo[br];
            unsigned bh[2] = {BH.x, BH.y};
            unsigned bl[2] = {BL.x, BL.y};
            MMA16816(acc[t], ah, bh);
            MMA16816(acc[t], ah, bl);
            MMA16816(acc[t], al, bh);
        }
    }

    int r0 = wm * 16 + gid;
    int node0 = n0 + r0, node1 = n0 + r0 + 8;
#pragma unroll
    for (int t = 0; t < 8; t++) {
        int col = wn * 64 + t * 8 + tig * 2;
        float bb0 = b[col], bb1 = b[col + 1];
        if (node0 < NN) *(float2*)(out + (size_t)node0 * HID + col) =
            make_float2(acc[t][0] + bb0, acc[t][1] + bb1);
        if (node1 < NN) *(float2*)(out + (size_t)node1 * HID + col) =
            make_float2(acc[t][2] + bb0, acc[t][3] + bb1);
    }
}

// ---------------------------------------------------------------------------
extern "C" void kernel_launch(void* const* d_in, const int* in_sizes, int n_in,
                              void* d_out, int out_size) {
    const float* x = (const float*)d_in[0];
    const void* ei = d_in[1];
    const float* ea = (const float*)d_in[2];
    const float* enc_W = (const float*)d_in[3];
    const float* enc_b = (const float*)d_in[4];
    const float* enc_g = (const float*)d_in[5];
    const float* enc_beta = (const float*)d_in[6];
    const float* msg_W1 = (const float*)d_in[7];
    const float* msg_b1 = (const float*)d_in[8];
    const float* msg_W2 = (const float*)d_in[9];
    const float* msg_b2 = (const float*)d_in[10];
    const float* upd_W1 = (const float*)d_in[11];
    const float* upd_b1 = (const float*)d_in[12];
    const float* upd_W2 = (const float*)d_in[13];
    const float* upd_b2 = (const float*)d_in[14];
    const float* ln_g = (const float*)d_in[15];
    const float* ln_beta = (const float*)d_in[16];
    const float* head_W = (const float*)d_in[17];
    const float* head_b = (const float*)d_in[18];
    float* out = (float*)d_out;

    static float* dP = nullptr;
    static float* dQ = nullptr;
    if (!dP) {
        cudaGetSymbolAddress((void**)&dP, g_P);
        cudaGetSymbolAddress((void**)&dQ, g_Q);
    }

    const int NB = (NN + 63) / 64;
    const int ZB = ((size_t)NN * HID + 255) / 256;

    // ---- layer 0; msg at launch index 3 so ncu profiles it ----
    init_aggr_kernel<<<ZB, 256>>>((const unsigned*)ei);
    enc_kernel<<<NN, 128>>>(x, enc_W, enc_b, enc_g, enc_beta);
    nodemm2_kernel<<<dim3(NB, 2), 256>>>(msg_W1, dP, dQ);
    msg_kernel<<<EE / 64, 256>>>(
        ei, ea,
        msg_W1 + (size_t)256 * HID, msg_b1,
        msg_W2, msg_b2);
    zero_deg_kernel<<<(NN + 255) / 256, 256>>>();
    deg_kernel<<<(EE + 255) / 256, 256>>>(ei);
    rdeg_kernel<<<(NN + 255) / 256, 256>>>();
    upd_kernel<<<NB, 256>>>(
        upd_W1, upd_b1, upd_W2, upd_b2, ln_g, ln_beta);

    // ---- layer 1 ----
    const float* W1_1 = msg_W1 + (size_t)272 * HID;
    nodemm2_kernel<<<dim3(NB, 2), 256>>>(W1_1, dP, dQ);
    init_aggr_kernel<<<ZB, 256>>>((const unsigned*)ei);
    msg_kernel<<<EE / 64, 256>>>(
        ei, ea,
        W1_1 + (size_t)256 * HID, msg_b1 + HID,
        msg_W2 + (size_t)HID * HID, msg_b2 + HID);
    upd_kernel<<<NB, 256>>>(
        upd_W1 + (size_t)256 * HID, upd_b1 + HID,
        upd_W2 + (size_t)HID * HID, upd_b2 + HID,
        ln_g + HID, ln_beta + HID);

    head_kernel<<<NB, 256>>>(head_W, head_b, out);
}

// round 16
// speedup vs baseline: 1.3676x; 1.0555x over previous
#include <cuda_runtime.h>
#include <cuda_bf16.h>
#include <cstdint>

#define NN 50000
#define EE 800000
#define HID 128

// Scratch (device globals — no allocation allowed)
__device__ float g_h[(size_t)NN * HID];
__device__ float g_aggr[(size_t)NN * HID];
__device__ float g_P[(size_t)NN * HID];
__device__ float g_Q[(size_t)NN * HID];
__device__ float g_rdeg[NN];
__device__ int g_ei_is64;
// packed split-bf16 weight fragment images (msg GEMMs)
__device__ __align__(16) unsigned gW2h[2 * 128 * 64];
__device__ __align__(16) unsigned gW2l[2 * 128 * 64];
__device__ __align__(16) unsigned gW1h[2 * 128 * 8];
__device__ __align__(16) unsigned gW1l[2 * 128 * 8];

typedef unsigned long long u64;

#define RED2(ptr, a, b) \
    asm volatile("red.global.add.v2.f32 [%0], {%1, %2};" \
                 :: "l"(ptr), "f"(a), "f"(b) : "memory")

#define MMA16816(cc, aa, bb) \
    asm volatile("mma.sync.aligned.m16n8k16.row.col.f32.bf16.bf16.f32 " \
                 "{%0,%1,%2,%3}, {%4,%5,%6,%7}, {%8,%9}, {%0,%1,%2,%3};" \
                 : "+f"(cc[0]), "+f"(cc[1]), "+f"(cc[2]), "+f"(cc[3]) \
                 : "r"(aa[0]), "r"(aa[1]), "r"(aa[2]), "r"(aa[3]), \
                   "r"(bb[0]), "r"(bb[1]))

// split float pair into bf16 hi-pack and bf16 residual-pack (x in low bits)
__device__ __forceinline__ void split2(float x, float y, unsigned& hi, unsigned& lo) {
    __nv_bfloat16 xh = __float2bfloat16_rn(x);
    __nv_bfloat16 yh = __float2bfloat16_rn(y);
    __nv_bfloat16 xl = __float2bfloat16_rn(x - __bfloat162float(xh));
    __nv_bfloat16 yl = __float2bfloat16_rn(y - __bfloat162float(yh));
    hi = ((unsigned)__bfloat16_as_ushort(yh) << 16) | __bfloat16_as_ushort(xh);
    lo = ((unsigned)__bfloat16_as_ushort(yl) << 16) | __bfloat16_as_ushort(xl);
}

// perm: k-pair p (0..7) -> u32 slot so that (tig, tig+4) are adjacent
__device__ __forceinline__ int permp(int p) { return 2 * (p & 3) + (p >> 2); }

__device__ __forceinline__ int load_ei(const void* ei, size_t idx, int is64) {
    int v = is64 ? (int)((const long long*)ei)[idx] : ((const int*)ei)[idx];
    return min(max(v, 0), NN - 1);
}

// ---------------------------------------------------------------------------
// init_aggr: zero g_aggr + dtype probe + pack msg weights (idempotent)
// ---------------------------------------------------------------------------
__global__ void init_aggr_kernel(const unsigned* __restrict__ raw,
                                 const float* __restrict__ msg_W1,
                                 const float* __restrict__ msg_W2) {
    size_t i = (size_t)blockIdx.x * blockDim.x + threadIdx.x;
    if (i < (size_t)NN * HID) g_aggr[i] = 0.f;
    if (blockIdx.x == 0 && threadIdx.x == 0) {
        int is64 = 1;
        for (int k = 0; k < 64; k++)
            if (raw[2 * k + 1] != 0u) { is64 = 0; break; }
        g_ei_is64 = is64;
    }
    // pack W2 (2 x 128n x 64 kpairs) and W1c (2 x 128n x 8 kpairs)
    int tid = (int)i;
    if (tid < 2 * 128 * 64) {
        int l = tid >> 13, r = tid & 8191;
        int n = r >> 6, p = r & 63;
        const float* W2 = msg_W2 + (size_t)l * 128 * 128;
        float w0 = W2[(size_t)(2 * p) * 128 + n];
        float w1 = W2[(size_t)(2 * p + 1) * 128 + n];
        unsigned hi, lo;
        split2(w0, w1, hi, lo);
        int c = p >> 3, pl = p & 7;
        gW2h[l * 8192 + n * 64 + c * 8 + permp(pl)] = hi;
        gW2l[l * 8192 + n * 64 + c * 8 + permp(pl)] = lo;
    } else if (tid < 2 * 128 * 64 + 2 * 128 * 8) {
        int r = tid - 2 * 128 * 64;
        int l = r >> 10; r &= 1023;
        int n = r >> 3, p = r & 7;
        const float* W1c = msg_W1 + (size_t)l * 272 * 128 + (size_t)256 * 128;
        float w0 = W1c[(size_t)(2 * p) * 128 + n];
        float w1 = W1c[(size_t)(2 * p + 1) * 128 + n];
        unsigned hi, lo;
        split2(w0, w1, hi, lo);
        gW1h[l * 1024 + n * 8 + permp(p)] = hi;
        gW1l[l * 1024 + n * 8 + permp(p)] = lo;
    }
}

// ---------------------------------------------------------------------------
__global__ void enc_kernel(const float* __restrict__ x, const float* __restrict__ W,
                           const float* __restrict__ b, const float* __restrict__ g,
                           const float* __restrict__ beta) {
    int node = blockIdx.x;
    int t = threadIdx.x;
    __shared__ float sx[32];
    __shared__ float red[8];
    if (t < 32) sx[t] = x[node * 32 + t];
    __syncthreads();
    float acc = b[t];
#pragma unroll
    for (int k = 0; k < 32; k++) acc = fmaf(sx[k], W[k * HID + t], acc);
    acc = fmaxf(acc, 0.f);
    float s = acc, sq = acc * acc;
#pragma unroll
    for (int o = 16; o; o >>= 1) {
        s += __shfl_xor_sync(0xffffffffu, s, o);
        sq += __shfl_xor_sync(0xffffffffu, sq, o);
    }
    int w = t >> 5;
    if ((t & 31) == 0) { red[w] = s; red[4 + w] = sq; }
    __syncthreads();
    s = red[0] + red[1] + red[2] + red[3];
    sq = red[4] + red[5] + red[6] + red[7];
    float mu = s * (1.f / HID);
    float var = sq * (1.f / HID) - mu * mu;
    g_h[(size_t)node * HID + t] = (acc - mu) * rsqrtf(var + 1e-5f) * g[t] + beta[t];
}

__global__ void zero_deg_kernel() {
    int i = blockIdx.x * blockDim.x + threadIdx.x;
    if (i < NN) g_rdeg[i] = 0.f;
}
__global__ void deg_kernel(const void* __restrict__ ei) {
    int e = blockIdx.x * blockDim.x + threadIdx.x;
    int is64 = g_ei_is64;
    if (e < EE) atomicAdd(&g_rdeg[load_ei(ei, (size_t)EE + e, is64)], 1.f);
}
__global__ void rdeg_kernel() {
    int i = blockIdx.x * blockDim.x + threadIdx.x;
    if (i < NN) g_rdeg[i] = 1.f / fmaxf(g_rdeg[i], 1.f);
}

// ---------------------------------------------------------------------------
// Node GEMM (mma): blockIdx.y: 0 -> P = h@W1[0:128], 1 -> Q = h@W1[128:256]
// (unchanged from R13, validated)
// ---------------------------------------------------------------------------
__global__ void __launch_bounds__(256)
nodemm2_kernel(const float* __restrict__ W1, float* __restrict__ P, float* __restrict__ Q) {
    __shared__ __align__(16) unsigned sB_hi[128 * 10];
    __shared__ __align__(16) unsigned sB_lo[128 * 10];
    __shared__ __align__(16) unsigned sA_hi[64 * 10];
    __shared__ __align__(16) unsigned sA_lo[64 * 10];

    const float* W = W1 + (size_t)blockIdx.y * 128 * HID;
    float* out = blockIdx.y ? Q : P;

    int tid = threadIdx.x;
    int lane = tid & 31, wid = tid >> 5;
    int gid = lane >> 2, tig = lane & 3;
    int wm = wid & 3, wn = wid >> 2;
    int n0 = blockIdx.x * 64;

    int le = tid >> 2, kq = tid & 3;
    int bn = tid & 127, bkh = tid >> 7;
    int lnode = min(n0 + le, NN - 1);

    const int q0 = permp(2 * kq), q1 = permp(2 * kq + 1);
    const int arow0 = (wm * 16 + gid) * 10 + 2 * tig;

    float acc[8][4];
#pragma unroll
    for (int t = 0; t < 8; t++)
#pragma unroll
        for (int j = 0; j < 4; j++) acc[t][j] = 0.f;

    for (int c = 0; c < 8; c++) {
        float4 v = *(const float4*)(g_h + (size_t)lnode * HID + c * 16 + kq * 4);
        float w[8];
        const float* wp = W + (size_t)(c * 16 + bkh * 8) * HID + bn;
#pragma unroll
        for (int kk = 0; kk < 8; kk++) w[kk] = wp[(size_t)kk * HID];
        __syncthreads();
        unsigned h0, l0, h1, l1;
        split2(v.x, v.y, h0, l0);
        split2(v.z, v.w, h1, l1);
        sA_hi[le * 10 + q0] = h0; sA_lo[le * 10 + q0] = l0;
        sA_hi[le * 10 + q1] = h1; sA_lo[le * 10 + q1] = l1;
#pragma unroll
        for (int j = 0; j < 4; j++) {
            unsigned hi, lo;
            split2(w[2 * j], w[2 * j + 1], hi, lo);
            int q = permp(bkh * 4 + j);
            sB_hi[bn * 10 + q] = hi;
            sB_lo[bn * 10 + q] = lo;
        }
        __syncthreads();
        uint2 AH0 = *(uint2*)&sA_hi[arow0];
        uint2 AH1 = *(uint2*)&sA_hi[arow0 + 80];
        uint2 AL0 = *(uint2*)&sA_lo[arow0];
        uint2 AL1 = *(uint2*)&sA_lo[arow0 + 80];
        unsigned ah[4] = {AH0.x, AH1.x, AH0.y, AH1.y};
        unsigned al[4] = {AL0.x, AL1.x, AL0.y, AL1.y};
#pragma unroll
        for (int t = 0; t < 8; t++) {
            int br = (wn * 64 + t * 8 + gid) * 10 + 2 * tig;
            uint2 BH = *(uint2*)&sB_hi[br];
            uint2 BL = *(uint2*)&sB_lo[br];
            unsigned bh[2] = {BH.x, BH.y};
            unsigned bl[2] = {BL.x, BL.y};
            MMA16816(acc[t], ah, bh);
            MMA16816(acc[t], ah, bl);
            MMA16816(acc[t], al, bh);
        }
    }

    int r0 = wm * 16 + gid;
    int node0 = n0 + r0, node1 = n0 + r0 + 8;
#pragma unroll
    for (int t = 0; t < 8; t++) {
        int col = wn * 64 + t * 8 + tig * 2;
        if (node0 < NN) *(float2*)(out + (size_t)node0 * HID + col) = make_float2(acc[t][0], acc[t][1]);
        if (node1 < NN) *(float2*)(out + (size_t)node1 * HID + col) = make_float2(acc[t][2], acc[t][3]);
    }
}

// ---------------------------------------------------------------------------
// Message kernel — 2(M)x4(N) warp grid; B-fragments via LDG from precomputed
// packed images (gW1/gW2, L1-resident). No weight conversion, no B smem,
// GEMM2 fully sync-free.
// ---------------------------------------------------------------------------
__global__ void __launch_bounds__(256)
msg_kernel(const void* __restrict__ ei, const float* __restrict__ ea,
           const unsigned* __restrict__ w1h, const unsigned* __restrict__ w1l,
           const unsigned* __restrict__ w2h, const unsigned* __restrict__ w2l,
           const float* __restrict__ b1, const float* __restrict__ b2) {
    __shared__ __align__(16) unsigned sH_hi[64 * 70];
    __shared__ __align__(16) unsigned sH_lo[64 * 70];
    __shared__ int s_src[64];
    __shared__ int s_tgt[64];

    int tid = threadIdx.x;
    int lane = tid & 31, wid = tid >> 5;
    int gid = lane >> 2, tig = lane & 3;
    int wm = wid >> 2;        // 0..1 : 32-row half
    int wn = wid & 3;         // 0..3 : 32-col group
    int e0 = blockIdx.x * 64;

    int le = tid >> 2;
    int kq = tid & 3;

    int is64 = g_ei_is64;
    if (tid < 64) s_src[tid] = load_ei(ei, (size_t)e0 + tid, is64);
    else if (tid < 128) s_tgt[tid - 64] = load_ei(ei, (size_t)EE + e0 + (tid - 64), is64);

    float acc[2][4][4];
#pragma unroll
    for (int mt = 0; mt < 2; mt++)
#pragma unroll
        for (int t = 0; t < 4; t++)
#pragma unroll
            for (int j = 0; j < 4; j++) acc[mt][t][j] = 0.f;

    unsigned* sA_hi = sH_hi;
    unsigned* sA_lo = sH_lo;

    const int q0 = permp(2 * kq), q1 = permp(2 * kq + 1);
    const int rr0 = wm * 32 + gid;
    const int rr1 = wm * 32 + 16 + gid;

    __syncthreads();

    // ================= GEMM1: K=16 (ea @ W1c), B from gW1 =================
    {
        const float* ap = ea + (size_t)(e0 + le) * 16 + kq * 4;
        float4 v = *(const float4*)ap;
        unsigned h0, l0, h1, l1;
        split2(v.x, v.y, h0, l0);
        split2(v.z, v.w, h1, l1);
        sA_hi[le * 10 + q0] = h0; sA_lo[le * 10 + q0] = l0;
        sA_hi[le * 10 + q1] = h1; sA_lo[le * 10 + q1] = l1;
        __syncthreads();

        unsigned ah[2][4], al[2][4];
#pragma unroll
        for (int mt = 0; mt < 2; mt++) {
            int a0 = (wm * 32 + mt * 16 + gid) * 10 + 2 * tig;
            uint2 AH0 = *(uint2*)&sA_hi[a0];
            uint2 AH1 = *(uint2*)&sA_hi[a0 + 80];
            uint2 AL0 = *(uint2*)&sA_lo[a0];
            uint2 AL1 = *(uint2*)&sA_lo[a0 + 80];
            ah[mt][0] = AH0.x; ah[mt][1] = AH1.x; ah[mt][2] = AH0.y; ah[mt][3] = AH1.y;
            al[mt][0] = AL0.x; al[mt][1] = AL1.x; al[mt][2] = AL0.y; al[mt][3] = AL1.y;
        }
#pragma unroll
        for (int t = 0; t < 4; t++) {
            int br = (wn * 32 + t * 8 + gid) * 8 + 2 * tig;
            uint2 BH = *(const uint2*)&w1h[br];
            uint2 BL = *(const uint2*)&w1l[br];
            unsigned bh[2] = {BH.x, BH.y};
            unsigned bl[2] = {BL.x, BL.y};
#pragma unroll
            for (int mt = 0; mt < 2; mt++) {
                MMA16816(acc[mt][t], ah[mt], bh);
                MMA16816(acc[mt][t], ah[mt], bl);
                MMA16816(acc[mt][t], al[mt], bh);
            }
        }
    }

    __syncthreads();  // GEMM1 mma reads done before sH overwrite

    // ---- += P[tgt] + Q[src] + b1, ReLU -> sH fragments ----
#pragma unroll
    for (int mt = 0; mt < 2; mt++) {
        int r0 = (mt ? rr1 : rr0);
        int n0t = s_tgt[r0], n0s = s_src[r0];
        int n1t = s_tgt[r0 + 8], n1s = s_src[r0 + 8];
        const float* P0 = g_P + (size_t)n0t * HID;
        const float* Q0 = g_Q + (size_t)n0s * HID;
        const float* P1 = g_P + (size_t)n1t * HID;
        const float* Q1 = g_Q + (size_t)n1s * HID;
#pragma unroll
        for (int t = 0; t < 4; t++) {
            int col = wn * 32 + t * 8 + tig * 2;
            float bb0 = b1[col], bb1 = b1[col + 1];
            float2 p0 = *(const float2*)(P0 + col);
            float2 qq0 = *(const float2*)(Q0 + col);
            float2 p1 = *(const float2*)(P1 + col);
            float2 qq1 = *(const float2*)(Q1 + col);
            float x0 = fmaxf(acc[mt][t][0] + bb0 + p0.x + qq0.x, 0.f);
            float x1 = fmaxf(acc[mt][t][1] + bb1 + p0.y + qq0.y, 0.f);
            float x2 = fmaxf(acc[mt][t][2] + bb0 + p1.x + qq1.x, 0.f);
            float x3 = fmaxf(acc[mt][t][3] + bb1 + p1.y + qq1.y, 0.f);
            int c2 = col >> 4;
            int q = permp((t & 1) * 4 + tig);
            unsigned hi0, lo0, hi1, lo1;
            split2(x0, x1, hi0, lo0);
            split2(x2, x3, hi1, lo1);
            sH_hi[r0 * 70 + c2 * 8 + q] = hi0;
            sH_lo[r0 * 70 + c2 * 8 + q] = lo0;
            sH_hi[(r0 + 8) * 70 + c2 * 8 + q] = hi1;
            sH_lo[(r0 + 8) * 70 + c2 * 8 + q] = lo1;
#pragma unroll
            for (int j = 0; j < 4; j++) acc[mt][t][j] = 0.f;
        }
    }
    __syncthreads();

    // ================= GEMM2: K=128, B from gW2 (sync-free) =================
    for (int c = 0; c < 8; c++) {
        unsigned ah[2][4], al[2][4];
#pragma unroll
        for (int mt = 0; mt < 2; mt++) {
            int ar = (wm * 32 + mt * 16 + gid) * 70 + c * 8 + 2 * tig;
            uint2 AH0 = *(uint2*)&sH_hi[ar];
            uint2 AH1 = *(uint2*)&sH_hi[ar + 560];
            uint2 AL0 = *(uint2*)&sH_lo[ar];
            uint2 AL1 = *(uint2*)&sH_lo[ar + 560];
            ah[mt][0] = AH0.x; ah[mt][1] = AH1.x; ah[mt][2] = AH0.y; ah[mt][3] = AH1.y;
            al[mt][0] = AL0.x; al[mt][1] = AL1.x; al[mt][2] = AL0.y; al[mt][3] = AL1.y;
        }
#pragma unroll
        for (int t = 0; t < 4; t++) {
            int br = (wn * 32 + t * 8 + gid) * 64 + c * 8 + 2 * tig;
            uint2 BH = *(const uint2*)&w2h[br];
            uint2 BL = *(const uint2*)&w2l[br];
            unsigned bh[2] = {BH.x, BH.y};
            unsigned bl[2] = {BL.x, BL.y};
#pragma unroll
            for (int mt = 0; mt < 2; mt++) {
                MMA16816(acc[mt][t], ah[mt], bh);
                MMA16816(acc[mt][t], ah[mt], bl);
                MMA16816(acc[mt][t], al[mt], bh);
            }
        }
    }

    // ---- scatter: m + b2 -> g_aggr[tgt] ----
#pragma unroll
    for (int mt = 0; mt < 2; mt++) {
        int r0 = (mt ? rr1 : rr0);
        int n0 = s_tgt[r0], n1 = s_tgt[r0 + 8];
#pragma unroll
        for (int t = 0; t < 4; t++) {
            int col = wn * 32 + t * 8 + tig * 2;
            float bb0 = b2[col], bb1 = b2[col + 1];
            RED2(g_aggr + (size_t)n0 * HID + col, acc[mt][t][0] + bb0, acc[mt][t][1] + bb1);
            RED2(g_aggr + (size_t)n1 * HID + col, acc[mt][t][2] + bb0, acc[mt][t][3] + bb1);
        }
    }
}

// ---------------------------------------------------------------------------
// Update kernel (unchanged from R13, validated)
// ---------------------------------------------------------------------------
__global__ void __launch_bounds__(256)
upd_kernel(const float* __restrict__ W1, const float* __restrict__ b1,
           const float* __restrict__ W2, const float* __restrict__ b2,
           const float* __restrict__ lng, const float* __restrict__ lnb) {
    __shared__ __align__(16) unsigned sB_hi[128 * 10];
    __shared__ __align__(16) unsigned sB_lo[128 * 10];
    __shared__ __align__(16) unsigned sHbuf[2 * 64 * 70];
    unsigned* sH_hi = sHbuf;
    unsigned* sH_lo = sHbuf + 64 * 70;
    float* sF = (float*)sHbuf;

    int tid = threadIdx.x;
    int lane = tid & 31, wid = tid >> 5;
    int gid = lane >> 2, tig = lane & 3;
    int wm = wid & 3, wn = wid >> 2;
    int n0 = blockIdx.x * 64;

    int le = tid >> 2, kq = tid & 3;
    int bn = tid & 127, bkh = tid >> 7;
    int lnode = min(n0 + le, NN - 1);
    float rd = g_rdeg[lnode];

    unsigned* sA_hi = sH_hi;
    unsigned* sA_lo = sH_lo;

    const int q0 = permp(2 * kq), q1 = permp(2 * kq + 1);
    const int arow0 = (wm * 16 + gid) * 10 + 2 * tig;

    float acc[8][4];
#pragma unroll
    for (int t = 0; t < 8; t++)
#pragma unroll
        for (int j = 0; j < 4; j++) acc[t][j] = 0.f;

    for (int c = 0; c < 16; c++) {
        const float* ap = (c < 8) ? g_h + (size_t)lnode * HID + c * 16 + kq * 4
                                  : g_aggr + (size_t)lnode * HID + (c - 8) * 16 + kq * 4;
        float4 v = *(const float4*)ap;
        if (c >= 8) { v.x *= rd; v.y *= rd; v.z *= rd; v.w *= rd; }
        float w[8];
        const float* wp = W1 + (size_t)(c * 16 + bkh * 8) * HID + bn;
#pragma unroll
        for (int kk = 0; kk < 8; kk++) w[kk] = wp[(size_t)kk * HID];
        __syncthreads();
        unsigned h0, l0, h1, l1;
        split2(v.x, v.y, h0, l0);
        split2(v.z, v.w, h1, l1);
        sA_hi[le * 10 + q0] = h0; sA_lo[le * 10 + q0] = l0;
        sA_hi[le * 10 + q1] = h1; sA_lo[le * 10 + q1] = l1;
#pragma unroll
        for (int j = 0; j < 4; j++) {
            unsigned hi, lo;
            split2(w[2 * j], w[2 * j + 1], hi, lo);
            int q = permp(bkh * 4 + j);
            sB_hi[bn * 10 + q] = hi;
            sB_lo[bn * 10 + q] = lo;
        }
        __syncthreads();
        uint2 AH0 = *(uint2*)&sA_hi[arow0];
        uint2 AH1 = *(uint2*)&sA_hi[arow0 + 80];
        uint2 AL0 = *(uint2*)&sA_lo[arow0];
        uint2 AL1 = *(uint2*)&sA_lo[arow0 + 80];
        unsigned ah[4] = {AH0.x, AH1.x, AH0.y, AH1.y};
        unsigned al[4] = {AL0.x, AL1.x, AL0.y, AL1.y};
#pragma unroll
        for (int t = 0; t < 8; t++) {
            int br = (wn * 64 + t * 8 + gid) * 10 + 2 * tig;
            uint2 BH = *(uint2*)&sB_hi[br];
            uint2 BL = *(uint2*)&sB_lo[br];
            unsigned bh[2] = {BH.x, BH.y};
            unsigned bl[2] = {BL.x, BL.y};
            MMA16816(acc[t], ah, bh);
            MMA16816(acc[t], ah, bl);
            MMA16816(acc[t], al, bh);
        }
    }
    __syncthreads();

    {
        int r0 = wm * 16 + gid;
#pragma unroll
        for (int t = 0; t < 8; t++) {
            int col = wn * 64 + t * 8 + tig * 2;
            float bb0 = b1[col], bb1 = b1[col + 1];
            float x0 = fmaxf(acc[t][0] + bb0, 0.f);
            float x1 = fmaxf(acc[t][1] + bb1, 0.f);
            float x2 = fmaxf(acc[t][2] + bb0, 0.f);
            float x3 = fmaxf(acc[t][3] + bb1, 0.f);
            int c2 = col >> 4;
            int q = permp((t & 1) * 4 + tig);
            unsigned hi0, lo0, hi1, lo1;
            split2(x0, x1, hi0, lo0);
            split2(x2, x3, hi1, lo1);
            sH_hi[r0 * 70 + c2 * 8 + q] = hi0;
            sH_lo[r0 * 70 + c2 * 8 + q] = lo0;
            sH_hi[(r0 + 8) * 70 + c2 * 8 + q] = hi1;
            sH_lo[(r0 + 8) * 70 + c2 * 8 + q] = lo1;
#pragma unroll
            for (int j = 0; j < 4; j++) acc[t][j] = 0.f;
        }
    }
    __syncthreads();

    for (int c = 0; c < 8; c++) {
        float w[8];
        const float* wp = W2 + (size_t)(c * 16 + bkh * 8) * HID + bn;
#pragma unroll
        for (int kk = 0; kk < 8; kk++) w[kk] = wp[(size_t)kk * HID];
        __syncthreads();
#pragma unroll
        for (int j = 0; j < 4; j++) {
            unsigned hi, lo;
            split2(w[2 * j], w[2 * j + 1], hi, lo);
            int q = permp(bkh * 4 + j);
            sB_hi[bn * 10 + q] = hi;
            sB_lo[bn * 10 + q] = lo;
        }
        __syncthreads();
        int ar = (wm * 16 + gid) * 70 + c * 8 + 2 * tig;
        uint2 AH0 = *(uint2*)&sH_hi[ar];
        uint2 AH1 = *(uint2*)&sH_hi[ar + 560];
        uint2 AL0 = *(uint2*)&sH_lo[ar];
        uint2 AL1 = *(uint2*)&sH_lo[ar + 560];
        unsigned ah[4] = {AH0.x, AH1.x, AH0.y, AH1.y};
        unsigned al[4] = {AL0.x, AL1.x, AL0.y, AL1.y};
#pragma unroll
        for (int t = 0; t < 8; t++) {
            int br = (wn * 64 + t * 8 + gid) * 10 + 2 * tig;
            uint2 BH = *(uint2*)&sB_hi[br];
            uint2 BL = *(uint2*)&sB_lo[br];
            unsigned bh[2] = {BH.x, BH.y};
            unsigned bl[2] = {BL.x, BL.y};
            MMA16816(acc[t], ah, bh);
            MMA16816(acc[t], ah, bl);
            MMA16816(acc[t], al, bh);
        }
    }
    __syncthreads();

    {
        int r0 = wm * 16 + gid;
        int node0 = min(n0 + r0, NN - 1), node1 = min(n0 + r0 + 8, NN - 1);
        const float* h0p = g_h + (size_t)node0 * HID;
        const float* h1p = g_h + (size_t)node1 * HID;
#pragma unroll
        for (int t = 0; t < 8; t++) {
            int col = wn * 64 + t * 8 + tig * 2;
            float bb0 = b2[col], bb1 = b2[col + 1];
            float2 ho0 = *(const float2*)(h0p + col);
            float2 ho1 = *(const float2*)(h1p + col);
            *(float2*)(sF + r0 * 132 + col) =
                make_float2(acc[t][0] + bb0 + ho0.x, acc[t][1] + bb1 + ho0.y);
            *(float2*)(sF + (r0 + 8) * 132 + col) =
                make_float2(acc[t][2] + bb0 + ho1.x, acc[t][3] + bb1 + ho1.y);
        }
    }
    __syncthreads();

    {
        int w = tid >> 5;
        for (int r = w; r < 64; r += 8) {
            int node = n0 + r;
            float4 v = *(float4*)(sF + r * 132 + lane * 4);
            float s = v.x + v.y + v.z + v.w;
            float sq = fmaf(v.x, v.x, fmaf(v.y, v.y, fmaf(v.z, v.z, v.w * v.w)));
#pragma unroll
            for (int o = 16; o; o >>= 1) {
                s += __shfl_xor_sync(0xffffffffu, s, o);
                sq += __shfl_xor_sync(0xffffffffu, sq, o);
            }
            float mu = s * (1.f / HID);
            float var = sq * (1.f / HID) - mu * mu;
            float rstd = rsqrtf(var + 1e-5f);
            if (node < NN) {
                int cc = lane * 4;
                float4 o;
                o.x = (v.x - mu) * rstd * lng[cc + 0] + lnb[cc + 0];
                o.y = (v.y - mu) * rstd * lng[cc + 1] + lnb[cc + 1];
                o.z = (v.z - mu) * rstd * lng[cc + 2] + lnb[cc + 2];
                o.w = (v.w - mu) * rstd * lng[cc + 3] + lnb[cc + 3];
                *(float4*)(g_h + (size_t)node * HID + cc) = o;
            }
        }
    }
}

// ---------------------------------------------------------------------------
// Head kernel (unchanged from R13, validated)
// ---------------------------------------------------------------------------
__global__ void __launch_bounds__(256)
head_kernel(const float* __restrict__ W, const float* __restrict__ b,
            float* __restrict__ out) {
    __shared__ __align__(16) unsigned sB_hi[128 * 10];
    __shared__ __align__(16) unsigned sB_lo[128 * 10];
    __shared__ __align__(16) unsigned sA_hi[64 * 10];
    __shared__ __align__(16) unsigned sA_lo[64 * 10];

    int tid = threadIdx.x;
    int lane = tid & 31, wid = tid >> 5;
    int gid = lane >> 2, tig = lane & 3;
    int wm = wid & 3, wn = wid >> 2;
    int n0 = blockIdx.x * 64;

    int le = tid >> 2, kq = tid & 3;
    int bn = tid & 127, bkh = tid >> 7;
    int lnode = min(n0 + le, NN - 1);

    const int q0 = permp(2 * kq), q1 = permp(2 * kq + 1);
    const int arow0 = (wm * 16 + gid) * 10 + 2 * tig;

    float acc[8][4];
#pragma unroll
    for (int t = 0; t < 8; t++)
#pragma unroll
        for (int j = 0; j < 4; j++) acc[t][j] = 0.f;

    for (int c = 0; c < 8; c++) {
        float4 v = *(const float4*)(g_h + (size_t)lnode * HID + c * 16 + kq * 4);
        float w[8];
        const float* wp = W + (size_t)(c * 16 + bkh * 8) * HID + bn;
#pragma unroll
        for (int kk = 0; kk < 8; kk++) w[kk] = wp[(size_t)kk * HID];
        __syncthreads();
        unsigned h0, l0, h1, l1;
        split2(v.x, v.y, h0, l0);
        split2(v.z, v.w, h1, l1);
        sA_hi[le * 10 + q0] = h0; sA_lo[le * 10 + q0] = l0;
        sA_hi[le * 10 + q1] = h1; sA_lo[le * 10 + q1] = l1;
#pragma unroll
        for (int j = 0; j < 4; j++) {
            unsigned hi, lo;
            split2(w[2 * j], w[2 * j + 1], hi, lo);
            int q = permp(bkh * 4 + j);
            sB_hi[bn * 10 + q] = hi;
            sB_lo[bn * 10 + q] = lo;
        }
        __syncthreads();
        uint2 AH0 = *(uint2*)&sA_hi[arow0];
        uint2 AH1 = *(uint2*)&sA_hi[arow0 + 80];
        uint2 AL0 = *(uint2*)&sA_lo[arow0];
        uint2 AL1 = *(uint2*)&sA_lo[arow0 + 80];
        unsigned ah[4] = {AH0.x, AH1.x, AH0.y, AH1.y};
        unsigned al[4] = {AL0.x, AL1.x, AL0.y, AL1.y};
#pragma unroll
        for (int t = 0; t < 8; t++) {
            int br = (wn * 64 + t * 8 + gid) * 10 + 2 * tig;
            uint2 BH = *(uint2*)&sB_hi[br];
            uint2 BL = *(uint2*)&sB_lo[br];
            unsigned bh[2] = {BH.x, BH.y};
            unsigned bl[2] = {BL.x, BL.y};
            MMA16816(acc[t], ah, bh);
            MMA16816(acc[t], ah, bl);
            MMA16816(acc[t], al, bh);
        }
    }

    int r0 = wm * 16 + gid;
    int node0 = n0 + r0, node1 = n0 + r0 + 8;
#pragma unroll
    for (int t = 0; t < 8; t++) {
        int col = wn * 64 + t * 8 + tig * 2;
        float bb0 = b[col], bb1 = b[col + 1];
        if (node0 < NN) *(float2*)(out + (size_t)node0 * HID + col) =
            make_float2(acc[t][0] + bb0, acc[t][1] + bb1);
        if (node1 < NN) *(float2*)(out + (size_t)node1 * HID + col) =
            make_float2(acc[t][2] + bb0, acc[t][3] + bb1);
    }
}

// ---------------------------------------------------------------------------
extern "C" void kernel_launch(void* const* d_in, const int* in_sizes, int n_in,
                              void* d_out, int out_size) {
    const float* x = (const float*)d_in[0];
    const void* ei = d_in[1];
    const float* ea = (const float*)d_in[2];
    const float* enc_W = (const float*)d_in[3];
    const float* enc_b = (const float*)d_in[4];
    const float* enc_g = (const float*)d_in[5];
    const float* enc_beta = (const float*)d_in[6];
    const float* msg_W1 = (const float*)d_in[7];
    const float* msg_b1 = (const float*)d_in[8];
    const float* msg_W2 = (const float*)d_in[9];
    const float* msg_b2 = (const float*)d_in[10];
    const float* upd_W1 = (const float*)d_in[11];
    const float* upd_b1 = (const float*)d_in[12];
    const float* upd_W2 = (const float*)d_in[13];
    const float* upd_b2 = (const float*)d_in[14];
    const float* ln_g = (const float*)d_in[15];
    const float* ln_beta = (const float*)d_in[16];
    const float* head_W = (const float*)d_in[17];
    const float* head_b = (const float*)d_in[18];
    float* out = (float*)d_out;

    static float* dP = nullptr;
    static float* dQ = nullptr;
    static unsigned *dW1h, *dW1l, *dW2h, *dW2l;
    if (!dP) {
        cudaGetSymbolAddress((void**)&dP, g_P);
        cudaGetSymbolAddress((void**)&dQ, g_Q);
        cudaGetSymbolAddress((void**)&dW1h, gW1h);
        cudaGetSymbolAddress((void**)&dW1l, gW1l);
        cudaGetSymbolAddress((void**)&dW2h, gW2h);
        cudaGetSymbolAddress((void**)&dW2l, gW2l);
    }

    const int NB = (NN + 63) / 64;
    const int ZB = ((size_t)NN * HID + 255) / 256;

    // ---- layer 0; msg stays at launch index 3 for ncu ----
    init_aggr_kernel<<<ZB, 256>>>((const unsigned*)ei, msg_W1, msg_W2);
    enc_kernel<<<NN, 128>>>(x, enc_W, enc_b, enc_g, enc_beta);
    nodemm2_kernel<<<dim3(NB, 2), 256>>>(msg_W1, dP, dQ);
    msg_kernel<<<EE / 64, 256>>>(
        ei, ea, dW1h, dW1l, dW2h, dW2l, msg_b1, msg_b2);
    zero_deg_kernel<<<(NN + 255) / 256, 256>>>();
    deg_kernel<<<(EE + 255) / 256, 256>>>(ei);
    rdeg_kernel<<<(NN + 255) / 256, 256>>>();
    upd_kernel<<<NB, 256>>>(
        upd_W1, upd_b1, upd_W2, upd_b2, ln_g, ln_beta);

    // ---- layer 1 ----
    const float* W1_1 = msg_W1 + (size_t)272 * HID;
    nodemm2_kernel<<<dim3(NB, 2), 256>>>(W1_1, dP, dQ);
    init_aggr_kernel<<<ZB, 256>>>((const unsigned*)ei, msg_W1, msg_W2);
    msg_kernel<<<EE / 64, 256>>>(
        ei, ea, dW1h + 1024, dW1l + 1024, dW2h + 8192, dW2l + 8192,
        msg_b1 + HID, msg_b2 + HID);
    upd_kernel<<<NB, 256>>>(
        upd_W1 + (size_t)256 * HID, upd_b1 + HID,
        upd_W2 + (size_t)HID * HID, upd_b2 + HID,
        ln_g + HID, ln_beta + HID);

    head_kernel<<<NB, 256>>>(head_W, head_b, out);
}